// round 1
// baseline (speedup 1.0000x reference)
#include <cuda_runtime.h>
#include <cstdint>

// ---------------- fixed problem dims ----------------
#define NVIS   192
#define NAUD   64
#define TT     128
#define FDIM   1024
#define CC     128
#define MV     (NVIS*TT)      // 24576 visual nodes
#define MA     (NAUD*TT)      // 8192  audio nodes
#define NNODE  (MV+MA)        // 32768
#define NC     (NNODE*CC)     // 4194304

// ---------------- scratch (device globals; no allocs allowed) ----------------
__device__ float g_x   [NC];
__device__ float g_xag [NC];
__device__ float g_P   [NC];
__device__ float g_Q   [NC];
__device__ float g_a   [NC];
__device__ float g_xv2 [NC];
__device__ float g_h   [NC];
__device__ float g_s   [NC];
__device__ float g_tmp [NC];
__device__ float g_xo  [NC];
__device__ float g_ares[NNODE];
__device__ int   g_cnt [NNODE];
__device__ float g_WP  [4*CC*CC];

// ---------------- utility kernels ----------------
__global__ void zero_f32(float* __restrict__ p, int n4) {
    int i = blockIdx.x * blockDim.x + threadIdx.x;
    if (i < n4) ((float4*)p)[i] = make_float4(0.f,0.f,0.f,0.f);
}
__global__ void zero_i32(int* __restrict__ p, int n) {
    int i = blockIdx.x * blockDim.x + threadIdx.x;
    if (i < n) p[i] = 0;
}
__global__ void relu_inplace(float* __restrict__ p, int n) {
    int i = blockIdx.x * blockDim.x + threadIdx.x;
    if (i < n) p[i] = fmaxf(p[i], 0.f);
}
// mean = s / max(cnt,1) in place
__global__ void mean_kernel(float* __restrict__ s, const int* __restrict__ cnt, int n) {
    int i = blockIdx.x * blockDim.x + threadIdx.x;
    if (i < n) {
        int c = cnt[i >> 7];
        s[i] = s[i] / (float)(c > 1 ? c : 1);
    }
}
// WP[conv] = W1[0:128,:] - W1[128:256,:]
__global__ void prep_wp(const float* __restrict__ w0, const float* __restrict__ w1,
                        const float* __restrict__ w2, const float* __restrict__ w3) {
    int i = blockIdx.x * blockDim.x + threadIdx.x;   // 4*16384
    if (i >= 4*CC*CC) return;
    int conv = i >> 14, j = i & 16383;
    const float* W = conv == 0 ? w0 : conv == 1 ? w1 : conv == 2 ? w2 : w3;
    g_WP[i] = W[j] - W[CC*CC + j];
}

// ---------------- generic fp32 GEMM: [M,K]@[K,128], BM=128 BN=128 BK=16 ----------------
template<bool BIAS, bool ADDC, bool RELU, bool ACCUM>
__global__ void __launch_bounds__(256) gemm_f32(
    const float* __restrict__ A, const float* __restrict__ W,
    const float* __restrict__ bias, const float* __restrict__ Cin,
    float* __restrict__ Cout, int M, int K)
{
    __shared__ float As[16][136];
    __shared__ float Bs[16][136];
    const int tid = threadIdx.x;
    const int block_row = blockIdx.x * 128;
    const int ty = tid >> 4, tx = tid & 15;
    float acc[8][8];
    #pragma unroll
    for (int i = 0; i < 8; i++)
        #pragma unroll
        for (int j = 0; j < 8; j++) acc[i][j] = 0.f;

    for (int k0 = 0; k0 < K; k0 += 16) {
        // A tile: 128 rows x 16 cols = 512 float4, 2 per thread; store transposed
        #pragma unroll
        for (int l = 0; l < 2; l++) {
            int idx = tid * 2 + l;
            int r = idx >> 2, c4 = (idx & 3) * 4;
            float4 v = *(const float4*)&A[(size_t)(block_row + r) * K + k0 + c4];
            As[c4+0][r] = v.x; As[c4+1][r] = v.y; As[c4+2][r] = v.z; As[c4+3][r] = v.w;
        }
        // W tile: 16 rows x 128 cols = 512 float4, 2 per thread
        #pragma unroll
        for (int l = 0; l < 2; l++) {
            int idx = tid * 2 + l;
            int r = idx >> 5, c4 = (idx & 31) * 4;
            *(float4*)&Bs[r][c4] = *(const float4*)&W[(size_t)(k0 + r) * CC + c4];
        }
        __syncthreads();
        #pragma unroll
        for (int k = 0; k < 16; k++) {
            float ra[8], rb[8];
            *(float4*)&ra[0] = *(const float4*)&As[k][ty*8];
            *(float4*)&ra[4] = *(const float4*)&As[k][ty*8+4];
            *(float4*)&rb[0] = *(const float4*)&Bs[k][tx*8];
            *(float4*)&rb[4] = *(const float4*)&Bs[k][tx*8+4];
            #pragma unroll
            for (int i = 0; i < 8; i++)
                #pragma unroll
                for (int j = 0; j < 8; j++) acc[i][j] += ra[i] * rb[j];
        }
        __syncthreads();
    }
    #pragma unroll
    for (int i = 0; i < 8; i++) {
        int row = block_row + ty*8 + i;
        #pragma unroll
        for (int j = 0; j < 8; j += 4) {
            int col = tx*8 + j;
            float4 v = make_float4(acc[i][j], acc[i][j+1], acc[i][j+2], acc[i][j+3]);
            if (BIAS) {
                v.x += bias[col]; v.y += bias[col+1]; v.z += bias[col+2]; v.w += bias[col+3];
            }
            if (ADDC) {
                float4 c = *(const float4*)&Cin[(size_t)row*CC + col];
                v.x += c.x; v.y += c.y; v.z += c.z; v.w += c.w;
            }
            if (RELU) {
                v.x = fmaxf(v.x, 0.f); v.y = fmaxf(v.y, 0.f);
                v.z = fmaxf(v.z, 0.f); v.w = fmaxf(v.w, 0.f);
            }
            if (ACCUM) {
                float4 o = *(const float4*)&Cout[(size_t)row*CC + col];
                v.x += o.x; v.y += o.y; v.z += o.z; v.w += o.w;
            }
            *(float4*)&Cout[(size_t)row*CC + col] = v;
        }
    }
}

// ---------------- edge kernels ----------------
// xa_g: relu(seg_max over attr==-3 of x[dst]+x[src])  (atomicMax of max(msg,0), init 0)
__global__ void edge_vpa(const int* __restrict__ src, const int* __restrict__ dst,
                         const int* __restrict__ attr, int E) {
    int e = blockIdx.x * 2 + (threadIdx.x >> 7);
    int c = threadIdx.x & 127;
    if (e >= E) return;
    if (attr[e] != -3) return;
    int s = src[e], d = dst[e];
    float m = g_x[(size_t)d*CC + c] + g_x[(size_t)s*CC + c];
    atomicMax((int*)&g_xag[(size_t)d*CC + c], __float_as_int(fmaxf(m, 0.f)));
}
// xv2 pre-relu: segment_sum over attr==3 of (a_res[src]*x[src] + x[dst])
__global__ void edge_acv(const int* __restrict__ src, const int* __restrict__ dst,
                         const int* __restrict__ attr, int E) {
    int e = blockIdx.x * 2 + (threadIdx.x >> 7);
    int c = threadIdx.x & 127;
    if (e >= E) return;
    if (attr[e] != 3) return;
    int s = src[e], d = dst[e];
    float msg = g_ares[s] * g_x[(size_t)s*CC + c] + g_x[(size_t)d*CC + c];
    atomicAdd(&g_xv2[(size_t)d*CC + c], msg);
}
// SAGE aggregation: s[dst] += h[src], cnt[dst] += 1 for edges in [lo,hi]
__global__ void edge_sage(const int* __restrict__ src, const int* __restrict__ dst,
                          const int* __restrict__ attr, int E, int lo, int hi) {
    int e = blockIdx.x * 2 + (threadIdx.x >> 7);
    int c = threadIdx.x & 127;
    if (e >= E) return;
    int a = attr[e];
    if (a < lo || a > hi) return;
    int s = src[e], d = dst[e];
    atomicAdd(&g_s[(size_t)d*CC + c], g_h[(size_t)s*CC + c]);
    if (c == 0) atomicAdd(&g_cnt[d], 1);
}

// EdgeConv 2nd layer + seg_max: out[dst] = max over edges of relu( relu(P[dst]+Q[src]) @ W2 + b2 )
// W2 half-column held in registers per thread; grid-stride over edges.
__global__ void __launch_bounds__(256) edge_conv(
    const int* __restrict__ src, const int* __restrict__ dst, const int* __restrict__ attr,
    int E, int lo, int hi,
    const float* __restrict__ W2, const float* __restrict__ b2,
    const float* __restrict__ P, const float* __restrict__ Q,
    float* __restrict__ out)
{
    __shared__ float zs[128];
    __shared__ float partial[128];
    const int tid  = threadIdx.x;
    const int c    = tid & 127;
    const int half = tid >> 7;
    float w[64];
    #pragma unroll
    for (int i = 0; i < 64; i++) w[i] = W2[(size_t)(half*64 + i)*CC + c];
    const float b2c = b2[c];

    for (int e = blockIdx.x; e < E; e += gridDim.x) {
        int a = attr[e];
        if (a < lo || a > hi) continue;       // uniform across block
        int s = src[e], d = dst[e];
        if (half == 0)
            zs[c] = fmaxf(P[(size_t)d*CC + c] + Q[(size_t)s*CC + c], 0.f);
        __syncthreads();
        float a0 = 0.f, a1 = 0.f, a2 = 0.f, a3 = 0.f;
        const float* zp = &zs[half*64];
        #pragma unroll
        for (int i = 0; i < 16; i++) {
            float4 z4 = *(const float4*)&zp[i*4];
            a0 += z4.x * w[4*i+0];
            a1 += z4.y * w[4*i+1];
            a2 += z4.z * w[4*i+2];
            a3 += z4.w * w[4*i+3];
        }
        float accv = (a0 + a1) + (a2 + a3);
        if (half == 1) partial[c] = accv;
        __syncthreads();
        if (half == 0) {
            float msg = accv + partial[c] + b2c;
            atomicMax((int*)&out[(size_t)d*CC + c], __float_as_int(fmaxf(msg, 0.f)));
        }
        __syncthreads();
    }
}

// a_res = a @ fc_W + fc_b  (one warp per node)
__global__ void ares_kernel(const float* __restrict__ fcW, const float* __restrict__ fcb) {
    int warp = (blockIdx.x * blockDim.x + threadIdx.x) >> 5;
    int lane = threadIdx.x & 31;
    if (warp >= NNODE) return;
    const float* ap = &g_a[(size_t)warp * CC];
    float acc = 0.f;
    #pragma unroll
    for (int k = 0; k < 4; k++) acc += ap[lane + 32*k] * fcW[lane + 32*k];
    #pragma unroll
    for (int o = 16; o > 0; o >>= 1) acc += __shfl_xor_sync(0xffffffffu, acc, o);
    if (lane == 0) g_ares[warp] = acc + fcb[0];
}

// final gather: out[g*T + t, :] = xo[g*step + t, :]
__global__ void gather_out(float* __restrict__ out, int total, int step) {
    int i = blockIdx.x * blockDim.x + threadIdx.x;
    if (i >= total) return;
    int c = i & 127;
    int r = i >> 7;
    int t = r % TT, g = r / TT;
    int node = g * step + t;
    out[i] = g_xo[(size_t)node * CC + c];
}

// ---------------- host orchestration ----------------
static inline float* sym(const void* s) {
    void* p = nullptr;
    cudaGetSymbolAddress(&p, (const void*)s);
    return (float*)p;
}

extern "C" void kernel_launch(void* const* d_in, const int* in_sizes, int n_in,
                              void* d_out, int out_size) {
    const float* x_visual = (const float*)d_in[0];
    const float* x_audio  = (const float*)d_in[1];
    const float* W011 = (const float*)d_in[2];  const float* b011 = (const float*)d_in[3];
    const float* W012 = (const float*)d_in[4];  const float* b012 = (const float*)d_in[5];
    const float* ecW1[4] = {(const float*)d_in[6],  (const float*)d_in[10],
                            (const float*)d_in[14], (const float*)d_in[18]};
    const float* ecb1[4] = {(const float*)d_in[7],  (const float*)d_in[11],
                            (const float*)d_in[15], (const float*)d_in[19]};
    const float* ecW2[4] = {(const float*)d_in[8],  (const float*)d_in[12],
                            (const float*)d_in[16], (const float*)d_in[20]};
    const float* ecb2[4] = {(const float*)d_in[9],  (const float*)d_in[13],
                            (const float*)d_in[17], (const float*)d_in[21]};
    const float* Wl  = (const float*)d_in[22];
    const float* bl  = (const float*)d_in[23];
    const float* Wr  = (const float*)d_in[24];
    const float* fcW = (const float*)d_in[25];
    const float* fcb = (const float*)d_in[26];
    const int*   eidx = (const int*)d_in[27];
    const int*   attr = (const int*)d_in[28];
    const int E = in_sizes[27] / 2;
    const int* srcp = eidx;
    const int* dstp = eidx + E;

    float* px   = sym(g_x);    float* pxag = sym(g_xag);
    float* pP   = sym(g_P);    float* pQ   = sym(g_Q);
    float* pa   = sym(g_a);    float* pxv2 = sym(g_xv2);
    float* ph   = sym(g_h);    float* ps   = sym(g_s);
    float* ptmp = sym(g_tmp);  float* pxo  = sym(g_xo);
    float* pwp  = sym(g_WP);
    int*   pcnt = (int*)sym(g_cnt);

    const int ZG = (NC/4 + 255) / 256;                 // zero grid (float4)
    const int EG = (E + 1) / 2;                        // 2 edges per 256-thr block
    const int CONV_GRID = 2048;

    // conv weight combine: WP = W1a - W1b
    prep_wp<<<(4*CC*CC + 255)/256, 256>>>(ecW1[0], ecW1[1], ecW1[2], ecW1[3]);

    // input projections -> g_x
    gemm_f32<true,false,false,false><<<MV/128, 256>>>(x_visual, W011, b011, nullptr, px, MV, FDIM);
    gemm_f32<true,false,false,false><<<MA/128, 256>>>(x_audio,  W012, b012, nullptr, px + (size_t)MV*CC, MA, FDIM);

    // xa_g = relu(seg_max over vpa edges of x[dst]+x[src])
    zero_f32<<<ZG, 256>>>(pxag, NC/4);
    edge_vpa<<<EG, 256>>>(srcp, dstp, attr, E);

    // convA: a = relu(EdgeConv(xa_g; attr==-2))
    gemm_f32<true,false,false,false><<<NNODE/128, 256>>>(pxag, pwp,            ecb1[0], nullptr, pP, NNODE, CC);
    gemm_f32<false,false,false,false><<<NNODE/128, 256>>>(pxag, ecW1[0]+CC*CC, nullptr, nullptr, pQ, NNODE, CC);
    zero_f32<<<ZG, 256>>>(pa, NC/4);
    edge_conv<<<CONV_GRID, 256>>>(srcp, dstp, attr, E, -2, -2, ecW2[0], ecb2[0], pP, pQ, pa);

    // a_res = a @ fc_W + fc_b
    ares_kernel<<<NNODE/8, 256>>>(fcW, fcb);

    // xv2 = relu(segment_sum over attr==3 of a_res[src]*x[src] + x[dst])
    zero_f32<<<ZG, 256>>>(pxv2, NC/4);
    edge_acv<<<EG, 256>>>(srcp, dstp, attr, E);
    relu_inplace<<<(NC + 255)/256, 256>>>(pxv2, NC);

    // output accumulator
    zero_f32<<<ZG, 256>>>(pxo, NC/4);

    const int LO[3] = { 0, -1, -1 };
    const int HI[3] = { 1,  0,  1 };
    for (int b = 0; b < 3; b++) {
        const int ci = b + 1;   // conv params ec1/ec2/ec3
        // h = relu(EdgeConv(xv2; mask_b))
        gemm_f32<true,false,false,false><<<NNODE/128, 256>>>(pxv2, pwp + ci*CC*CC,    ecb1[ci], nullptr, pP, NNODE, CC);
        gemm_f32<false,false,false,false><<<NNODE/128, 256>>>(pxv2, ecW1[ci]+CC*CC, nullptr,  nullptr, pQ, NNODE, CC);
        zero_f32<<<ZG, 256>>>(ph, NC/4);
        edge_conv<<<CONV_GRID, 256>>>(srcp, dstp, attr, E, LO[b], HI[b], ecW2[ci], ecb2[ci], pP, pQ, ph);
        // SAGE: mean of h[src] over mask
        zero_f32<<<ZG, 256>>>(ps, NC/4);
        zero_i32<<<(NNODE + 255)/256, 256>>>(pcnt, NNODE);
        edge_sage<<<EG, 256>>>(srcp, dstp, attr, E, LO[b], HI[b]);
        mean_kernel<<<(NC + 255)/256, 256>>>(ps, pcnt, NC);
        // tmp = mean@Wl + bl ; xo += relu(tmp + h@Wr)
        gemm_f32<true,false,false,false><<<NNODE/128, 256>>>(ps, Wl, bl, nullptr, ptmp, NNODE, CC);
        gemm_f32<false,true,true,true><<<NNODE/128, 256>>>(ph, Wr, nullptr, ptmp, pxo, NNODE, CC);
    }

    // gather main-speaker visual nodes
    int groups = out_size / (TT * CC);      // 64
    int step   = MV / groups;               // speakers*T = 384
    gather_out<<<(out_size + 255)/256, 256>>>((float*)d_out, out_size, step);
}

// round 3
// speedup vs baseline: 1.2303x; 1.2303x over previous
#include <cuda_runtime.h>
#include <cstdint>

// ---------------- fixed problem dims ----------------
#define NVIS   192
#define NAUD   64
#define TT     128
#define FDIM   1024
#define CC     128
#define MV     (NVIS*TT)      // 24576 visual nodes
#define MA     (NAUD*TT)      // 8192  audio nodes
#define NNODE  (MV+MA)        // 32768
#define NC     (NNODE*CC)     // 4194304

// ---------------- scratch (device globals; no allocs allowed) ----------------
__device__ float g_x   [NC];
__device__ float g_xag [NC];
__device__ float g_P   [NC];
__device__ float g_Q   [NC];
__device__ float g_a   [NC];
__device__ float g_xv2 [NC];
__device__ float g_h   [NC];
__device__ float g_s   [NC];
__device__ float g_tmp [NC];
__device__ float g_xo  [NC];
__device__ float g_ares[NNODE];
__device__ int   g_cnt [NNODE];
__device__ float g_WP  [4*CC*CC];

// ---------------- small helpers ----------------
__device__ __forceinline__ uint32_t f2tf(float x) {
    uint32_t r;
    asm("cvt.rna.tf32.f32 %0, %1;\n" : "=r"(r) : "f"(x));
    return r;
}
__device__ __forceinline__ void cpasync16(void* dst, const void* src) {
    uint32_t d = (uint32_t)__cvta_generic_to_shared(dst);
    asm volatile("cp.async.cg.shared.global [%0], [%1], 16;\n" :: "r"(d), "l"(src));
}
#define CP_COMMIT()  asm volatile("cp.async.commit_group;\n")
#define CP_WAIT(n)   asm volatile("cp.async.wait_group %0;\n" :: "n"(n))

__device__ __forceinline__ void mma_tf32(float* c, const uint32_t* a, const uint32_t* b) {
    asm volatile(
        "mma.sync.aligned.m16n8k8.row.col.f32.tf32.tf32.f32 "
        "{%0,%1,%2,%3}, {%4,%5,%6,%7}, {%8,%9}, {%0,%1,%2,%3};\n"
        : "+f"(c[0]), "+f"(c[1]), "+f"(c[2]), "+f"(c[3])
        : "r"(a[0]), "r"(a[1]), "r"(a[2]), "r"(a[3]), "r"(b[0]), "r"(b[1]));
}

// ---------------- utility kernels ----------------
__global__ void relu_inplace(float* __restrict__ p, int n) {
    int i = blockIdx.x * blockDim.x + threadIdx.x;
    if (i < n) p[i] = fmaxf(p[i], 0.f);
}
__global__ void mean_kernel(float* __restrict__ s, const int* __restrict__ cnt, int n) {
    int i = blockIdx.x * blockDim.x + threadIdx.x;
    if (i < n) {
        int c = cnt[i >> 7];
        s[i] = s[i] / (float)(c > 1 ? c : 1);
    }
}
// WP[conv] = W1[0:128,:] - W1[128:256,:]
__global__ void prep_wp(const float* __restrict__ w0, const float* __restrict__ w1,
                        const float* __restrict__ w2, const float* __restrict__ w3) {
    int i = blockIdx.x * blockDim.x + threadIdx.x;
    if (i >= 4*CC*CC) return;
    int conv = i >> 14, j = i & 16383;
    const float* W = conv == 0 ? w0 : conv == 1 ? w1 : conv == 2 ? w2 : w3;
    g_WP[i] = W[j] - W[CC*CC + j];
}

// ---------------- tf32 tensor-core GEMM: [M,K]@[K,128] ----------------
// BM=128 BN=128 BK=16, 256 threads (8 warps: 4x2), mma.m16n8k8, cp.async double buffer.
template<bool BIAS, bool ADDC, bool RELU, bool ACCUM>
__global__ void __launch_bounds__(256) gemm_tf32(
    const float* __restrict__ A, const float* __restrict__ W,
    const float* __restrict__ bias, const float* __restrict__ Cin,
    float* __restrict__ Cout, int M, int K)
{
    __shared__ float As[2][128][20];   // padded: 20 floats/row
    __shared__ float Bs[2][16][136];   // padded: 136 floats/row (conflict-free frag loads)
    const int tid  = threadIdx.x;
    const int warp = tid >> 5, lane = tid & 31;
    const int wm = warp >> 1;           // 0..3  (32 rows each)
    const int wn = warp & 1;            // 0..1  (64 cols each)
    const int block_row = blockIdx.x * 128;
    const int lq = lane >> 2;           // 0..7
    const int lr = lane & 3;            // 0..3

    float acc[2][8][4];
    #pragma unroll
    for (int mt = 0; mt < 2; mt++)
        #pragma unroll
        for (int nt = 0; nt < 8; nt++)
            #pragma unroll
            for (int i = 0; i < 4; i++) acc[mt][nt][i] = 0.f;

    // tile loader
    const int a_r  = (tid * 2) >> 2;          // rows for the 2 float4 A loads (consecutive idx)
    // we issue 2 loads with idx = tid*2, tid*2+1
    const int nk = K >> 4;

    // stage 0
    {
        #pragma unroll
        for (int l = 0; l < 2; l++) {
            int idx = tid * 2 + l;
            int r = idx >> 2, c4 = (idx & 3) * 4;
            cpasync16(&As[0][r][c4], &A[(size_t)(block_row + r) * K + c4]);
        }
        #pragma unroll
        for (int l = 0; l < 2; l++) {
            int idx = tid * 2 + l;
            int r = idx >> 5, c4 = (idx & 31) * 4;
            cpasync16(&Bs[0][r][c4], &W[(size_t)r * CC + c4]);
        }
        CP_COMMIT();
    }

    for (int kk = 0; kk < nk; kk++) {
        int st = kk & 1;
        if (kk + 1 < nk) {
            int ns = st ^ 1, k0 = (kk + 1) * 16;
            #pragma unroll
            for (int l = 0; l < 2; l++) {
                int idx = tid * 2 + l;
                int r = idx >> 2, c4 = (idx & 3) * 4;
                cpasync16(&As[ns][r][c4], &A[(size_t)(block_row + r) * K + k0 + c4]);
            }
            #pragma unroll
            for (int l = 0; l < 2; l++) {
                int idx = tid * 2 + l;
                int r = idx >> 5, c4 = (idx & 31) * 4;
                cpasync16(&Bs[ns][r][c4], &W[(size_t)(k0 + r) * CC + c4]);
            }
            CP_COMMIT();
            CP_WAIT(1);
        } else {
            CP_WAIT(0);
        }
        __syncthreads();

        #pragma unroll
        for (int ks = 0; ks < 2; ks++) {
            const int k0 = ks * 8;
            uint32_t af[2][4], bf[8][2];
            const int arow0 = wm * 32 + lq;
            #pragma unroll
            for (int mt = 0; mt < 2; mt++) {
                int r = arow0 + mt * 16;
                af[mt][0] = f2tf(As[st][r    ][k0 + lr    ]);
                af[mt][1] = f2tf(As[st][r + 8][k0 + lr    ]);
                af[mt][2] = f2tf(As[st][r    ][k0 + lr + 4]);
                af[mt][3] = f2tf(As[st][r + 8][k0 + lr + 4]);
            }
            #pragma unroll
            for (int nt = 0; nt < 8; nt++) {
                int col = wn * 64 + nt * 8 + lq;
                bf[nt][0] = f2tf(Bs[st][k0 + lr    ][col]);
                bf[nt][1] = f2tf(Bs[st][k0 + lr + 4][col]);
            }
            #pragma unroll
            for (int mt = 0; mt < 2; mt++)
                #pragma unroll
                for (int nt = 0; nt < 8; nt++)
                    mma_tf32(acc[mt][nt], af[mt], bf[nt]);
        }
        __syncthreads();
    }
    (void)a_r;

    // epilogue
    #pragma unroll
    for (int mt = 0; mt < 2; mt++) {
        #pragma unroll
        for (int half = 0; half < 2; half++) {
            int row = block_row + wm * 32 + mt * 16 + lq + half * 8;
            #pragma unroll
            for (int nt = 0; nt < 8; nt++) {
                int col = wn * 64 + nt * 8 + lr * 2;
                float v0 = acc[mt][nt][half * 2 + 0];
                float v1 = acc[mt][nt][half * 2 + 1];
                if (BIAS) { v0 += bias[col]; v1 += bias[col + 1]; }
                if (ADDC) {
                    float2 c = *(const float2*)&Cin[(size_t)row * CC + col];
                    v0 += c.x; v1 += c.y;
                }
                if (RELU) { v0 = fmaxf(v0, 0.f); v1 = fmaxf(v1, 0.f); }
                if (ACCUM) {
                    float2 o = *(const float2*)&Cout[(size_t)row * CC + col];
                    v0 += o.x; v1 += o.y;
                }
                *(float2*)&Cout[(size_t)row * CC + col] = make_float2(v0, v1);
            }
        }
    }
}

// ---------------- edge kernels ----------------
__global__ void edge_vpa(const int* __restrict__ src, const int* __restrict__ dst,
                         const int* __restrict__ attr, int E) {
    int e = blockIdx.x * 2 + (threadIdx.x >> 7);
    int c = threadIdx.x & 127;
    if (e >= E) return;
    if (attr[e] != -3) return;
    int s = src[e], d = dst[e];
    float m = g_x[(size_t)d*CC + c] + g_x[(size_t)s*CC + c];
    atomicMax((int*)&g_xag[(size_t)d*CC + c], __float_as_int(fmaxf(m, 0.f)));
}
__global__ void edge_acv(const int* __restrict__ src, const int* __restrict__ dst,
                         const int* __restrict__ attr, int E) {
    int e = blockIdx.x * 2 + (threadIdx.x >> 7);
    int c = threadIdx.x & 127;
    if (e >= E) return;
    if (attr[e] != 3) return;
    int s = src[e], d = dst[e];
    float msg = g_ares[s] * g_x[(size_t)s*CC + c] + g_x[(size_t)d*CC + c];
    atomicAdd(&g_xv2[(size_t)d*CC + c], msg);
}
__global__ void edge_sage(const int* __restrict__ src, const int* __restrict__ dst,
                          const int* __restrict__ attr, int E, int lo, int hi) {
    int e = blockIdx.x * 2 + (threadIdx.x >> 7);
    int c = threadIdx.x & 127;
    if (e >= E) return;
    int a = attr[e];
    if (a < lo || a > hi) return;
    int s = src[e], d = dst[e];
    atomicAdd(&g_s[(size_t)d*CC + c], g_h[(size_t)s*CC + c]);
    if (c == 0) atomicAdd(&g_cnt[d], 1);
}

// EdgeConv 2nd layer + seg_max
__global__ void __launch_bounds__(256) edge_conv(
    const int* __restrict__ src, const int* __restrict__ dst, const int* __restrict__ attr,
    int E, int lo, int hi,
    const float* __restrict__ W2, const float* __restrict__ b2,
    const float* __restrict__ P, const float* __restrict__ Q,
    float* __restrict__ out)
{
    __shared__ float zs[128];
    __shared__ float partial[128];
    const int tid  = threadIdx.x;
    const int c    = tid & 127;
    const int half = tid >> 7;
    float w[64];
    #pragma unroll
    for (int i = 0; i < 64; i++) w[i] = W2[(size_t)(half*64 + i)*CC + c];
    const float b2c = b2[c];

    for (int e = blockIdx.x; e < E; e += gridDim.x) {
        int a = attr[e];
        if (a < lo || a > hi) continue;
        int s = src[e], d = dst[e];
        if (half == 0)
            zs[c] = fmaxf(P[(size_t)d*CC + c] + Q[(size_t)s*CC + c], 0.f);
        __syncthreads();
        float a0 = 0.f, a1 = 0.f, a2 = 0.f, a3 = 0.f;
        const float* zp = &zs[half*64];
        #pragma unroll
        for (int i = 0; i < 16; i++) {
            float4 z4 = *(const float4*)&zp[i*4];
            a0 += z4.x * w[4*i+0];
            a1 += z4.y * w[4*i+1];
            a2 += z4.z * w[4*i+2];
            a3 += z4.w * w[4*i+3];
        }
        float accv = (a0 + a1) + (a2 + a3);
        if (half == 1) partial[c] = accv;
        __syncthreads();
        if (half == 0) {
            float msg = accv + partial[c] + b2c;
            atomicMax((int*)&out[(size_t)d*CC + c], __float_as_int(fmaxf(msg, 0.f)));
        }
        __syncthreads();
    }
}

// a_res = a @ fc_W + fc_b  (one warp per node)
__global__ void ares_kernel(const float* __restrict__ fcW, const float* __restrict__ fcb) {
    int warp = (blockIdx.x * blockDim.x + threadIdx.x) >> 5;
    int lane = threadIdx.x & 31;
    if (warp >= NNODE) return;
    const float* ap = &g_a[(size_t)warp * CC];
    float acc = 0.f;
    #pragma unroll
    for (int k = 0; k < 4; k++) acc += ap[lane + 32*k] * fcW[lane + 32*k];
    #pragma unroll
    for (int o = 16; o > 0; o >>= 1) acc += __shfl_xor_sync(0xffffffffu, acc, o);
    if (lane == 0) g_ares[warp] = acc + fcb[0];
}

__global__ void gather_out(float* __restrict__ out, int total, int step) {
    int i = blockIdx.x * blockDim.x + threadIdx.x;
    if (i >= total) return;
    int c = i & 127;
    int r = i >> 7;
    int t = r % TT, g = r / TT;
    int node = g * step + t;
    out[i] = g_xo[(size_t)node * CC + c];
}

// ---------------- host orchestration ----------------
static inline float* sym(const void* s) {
    void* p = nullptr;
    cudaGetSymbolAddress(&p, (const void*)s);
    return (float*)p;
}

extern "C" void kernel_launch(void* const* d_in, const int* in_sizes, int n_in,
                              void* d_out, int out_size) {
    const float* x_visual = (const float*)d_in[0];
    const float* x_audio  = (const float*)d_in[1];
    const float* W011 = (const float*)d_in[2];  const float* b011 = (const float*)d_in[3];
    const float* W012 = (const float*)d_in[4];  const float* b012 = (const float*)d_in[5];
    const float* ecW1[4] = {(const float*)d_in[6],  (const float*)d_in[10],
                            (const float*)d_in[14], (const float*)d_in[18]};
    const float* ecb1[4] = {(const float*)d_in[7],  (const float*)d_in[11],
                            (const float*)d_in[15], (const float*)d_in[19]};
    const float* ecW2[4] = {(const float*)d_in[8],  (const float*)d_in[12],
                            (const float*)d_in[16], (const float*)d_in[20]};
    const float* ecb2[4] = {(const float*)d_in[9],  (const float*)d_in[13],
                            (const float*)d_in[17], (const float*)d_in[21]};
    const float* Wl  = (const float*)d_in[22];
    const float* bl  = (const float*)d_in[23];
    const float* Wr  = (const float*)d_in[24];
    const float* fcW = (const float*)d_in[25];
    const float* fcb = (const float*)d_in[26];
    const int*   eidx = (const int*)d_in[27];
    const int*   attr = (const int*)d_in[28];
    const int E = in_sizes[27] / 2;
    const int* srcp = eidx;
    const int* dstp = eidx + E;

    float* px   = sym(g_x);    float* pxag = sym(g_xag);
    float* pP   = sym(g_P);    float* pQ   = sym(g_Q);
    float* pa   = sym(g_a);    float* pxv2 = sym(g_xv2);
    float* ph   = sym(g_h);    float* ps   = sym(g_s);
    float* ptmp = sym(g_tmp);  float* pxo  = sym(g_xo);
    float* pwp  = sym(g_WP);
    int*   pcnt = (int*)sym(g_cnt);

    const int EG = (E + 1) / 2;
    const int CONV_GRID = 2048;
    const size_t NCB = (size_t)NC * sizeof(float);

    prep_wp<<<(4*CC*CC + 255)/256, 256>>>(ecW1[0], ecW1[1], ecW1[2], ecW1[3]);

    // input projections -> g_x
    gemm_tf32<true,false,false,false><<<MV/128, 256>>>(x_visual, W011, b011, nullptr, px, MV, FDIM);
    gemm_tf32<true,false,false,false><<<MA/128, 256>>>(x_audio,  W012, b012, nullptr, px + (size_t)MV*CC, MA, FDIM);

    // xa_g = relu(seg_max over vpa edges of x[dst]+x[src])
    cudaMemsetAsync(pxag, 0, NCB);
    edge_vpa<<<EG, 256>>>(srcp, dstp, attr, E);

    // convA: a = relu(EdgeConv(xa_g; attr==-2))
    gemm_tf32<true,false,false,false><<<NNODE/128, 256>>>(pxag, pwp,            ecb1[0], nullptr, pP, NNODE, CC);
    gemm_tf32<false,false,false,false><<<NNODE/128, 256>>>(pxag, ecW1[0]+CC*CC, nullptr, nullptr, pQ, NNODE, CC);
    cudaMemsetAsync(pa, 0, NCB);
    edge_conv<<<CONV_GRID, 256>>>(srcp, dstp, attr, E, -2, -2, ecW2[0], ecb2[0], pP, pQ, pa);

    ares_kernel<<<NNODE/8, 256>>>(fcW, fcb);

    // xv2 = relu(segment_sum over attr==3 of a_res[src]*x[src] + x[dst])
    cudaMemsetAsync(pxv2, 0, NCB);
    edge_acv<<<EG, 256>>>(srcp, dstp, attr, E);
    relu_inplace<<<(NC + 255)/256, 256>>>(pxv2, NC);

    cudaMemsetAsync(pxo, 0, NCB);

    const int LO[3] = { 0, -1, -1 };
    const int HI[3] = { 1,  0,  1 };
    for (int b = 0; b < 3; b++) {
        const int ci = b + 1;
        gemm_tf32<true,false,false,false><<<NNODE/128, 256>>>(pxv2, pwp + ci*CC*CC, ecb1[ci], nullptr, pP, NNODE, CC);
        gemm_tf32<false,false,false,false><<<NNODE/128, 256>>>(pxv2, ecW1[ci]+CC*CC, nullptr, nullptr, pQ, NNODE, CC);
        cudaMemsetAsync(ph, 0, NCB);
        edge_conv<<<CONV_GRID, 256>>>(srcp, dstp, attr, E, LO[b], HI[b], ecW2[ci], ecb2[ci], pP, pQ, ph);
        cudaMemsetAsync(ps, 0, NCB);
        cudaMemsetAsync(pcnt, 0, NNODE * sizeof(int));
        edge_sage<<<EG, 256>>>(srcp, dstp, attr, E, LO[b], HI[b]);
        mean_kernel<<<(NC + 255)/256, 256>>>(ps, pcnt, NC);
        gemm_tf32<true,false,false,false><<<NNODE/128, 256>>>(ps, Wl, bl, nullptr, ptmp, NNODE, CC);
        gemm_tf32<false,true,true,true><<<NNODE/128, 256>>>(ph, Wr, nullptr, ptmp, pxo, NNODE, CC);
    }

    int groups = out_size / (TT * CC);
    int step   = MV / groups;
    gather_out<<<(out_size + 255)/256, 256>>>((float*)d_out, out_size, step);
}

// round 6
// speedup vs baseline: 3.6443x; 2.9621x over previous
#include <cuda_runtime.h>
#include <cstdint>

// ---------------- fixed problem dims ----------------
#define NVIS   192
#define NAUD   64
#define TT     128
#define FDIM   1024
#define CC     128
#define MV     (NVIS*TT)      // 24576 visual nodes
#define MA     (NAUD*TT)      // 8192  audio nodes
#define NNODE  (MV+MA)        // 32768
#define NC     (NNODE*CC)     // 4194304
#define EMAX   262144

// ---------------- scratch (device globals; no allocs allowed) ----------------
__device__ float g_x   [NC];
__device__ float g_xag [NC];
__device__ float g_P   [NC];
__device__ float g_Q   [NC];
__device__ float g_a   [NC];
__device__ float g_xv2 [NC];
__device__ float g_h   [NC];
__device__ float g_s   [NC];
__device__ float g_tmp [NC];
__device__ float g_xo  [NC];
__device__ float g_ares[NNODE];
__device__ int   g_cnt [NNODE];
__device__ float g_WP  [4*CC*CC];
__device__ int2  g_elist[6][EMAX];   // 0:vpa(-3) 1:audio(-2) 2:acv(3) 3:[0,1] 4:[-1,0] 5:[-1,1]
__device__ int   g_ecnt[6];

// ---------------- small helpers ----------------
__device__ __forceinline__ uint32_t f2tf(float x) {
    uint32_t r;
    asm("cvt.rna.tf32.f32 %0, %1;\n" : "=r"(r) : "f"(x));
    return r;
}
__device__ __forceinline__ void cpasync16(void* dst, const void* src) {
    uint32_t d = (uint32_t)__cvta_generic_to_shared(dst);
    asm volatile("cp.async.cg.shared.global [%0], [%1], 16;\n" :: "r"(d), "l"(src));
}
#define CP_COMMIT()  asm volatile("cp.async.commit_group;\n")
#define CP_WAIT(n)   asm volatile("cp.async.wait_group %0;\n" :: "n"(n))

__device__ __forceinline__ void mma_tf32(float* c, const uint32_t* a, const uint32_t* b) {
    asm volatile(
        "mma.sync.aligned.m16n8k8.row.col.f32.tf32.tf32.f32 "
        "{%0,%1,%2,%3}, {%4,%5,%6,%7}, {%8,%9}, {%0,%1,%2,%3};\n"
        : "+f"(c[0]), "+f"(c[1]), "+f"(c[2]), "+f"(c[3])
        : "r"(a[0]), "r"(a[1]), "r"(a[2]), "r"(a[3]), "r"(b[0]), "r"(b[1]));
}

// ---------------- utility kernels ----------------
__global__ void relu_inplace(float* __restrict__ p, int n) {
    int i = blockIdx.x * blockDim.x + threadIdx.x;
    if (i < n) p[i] = fmaxf(p[i], 0.f);
}
__global__ void mean_kernel(float* __restrict__ s, const int* __restrict__ cnt, int n) {
    int i = blockIdx.x * blockDim.x + threadIdx.x;
    if (i < n) {
        int c = cnt[i >> 7];
        s[i] = s[i] / (float)(c > 1 ? c : 1);
    }
}
__global__ void prep_wp(const float* __restrict__ w0, const float* __restrict__ w1,
                        const float* __restrict__ w2, const float* __restrict__ w3) {
    int i = blockIdx.x * blockDim.x + threadIdx.x;
    if (i >= 4*CC*CC) return;
    int conv = i >> 14, j = i & 16383;
    const float* W = conv == 0 ? w0 : conv == 1 ? w1 : conv == 2 ? w2 : w3;
    g_WP[i] = W[j] - W[CC*CC + j];
}

// ---------------- edge compaction (warp-aggregated) ----------------
__global__ void compact_edges(const int* __restrict__ src, const int* __restrict__ dst,
                              const int* __restrict__ attr, int E) {
    int e = blockIdx.x * blockDim.x + threadIdx.x;
    if (e >= E) return;                       // E multiple of 256: warps are full
    int a = attr[e];
    int2 sd = make_int2(src[e], dst[e]);
    bool pr[6];
    pr[0] = (a == -3);
    pr[1] = (a == -2);
    pr[2] = (a ==  3);
    pr[3] = (a >=  0) && (a <= 1);
    pr[4] = (a >= -1) && (a <= 0);
    pr[5] = (a >= -1) && (a <= 1);
    int lane = threadIdx.x & 31;
    #pragma unroll
    for (int i = 0; i < 6; i++) {
        unsigned mask = __ballot_sync(0xffffffffu, pr[i]);
        if (pr[i]) {
            int leader = __ffs(mask) - 1;
            int pos = 0;
            if (lane == leader) pos = atomicAdd(&g_ecnt[i], __popc(mask));
            pos = __shfl_sync(mask, pos, leader);
            int rank = __popc(mask & ((1u << lane) - 1));
            g_elist[i][pos + rank] = sd;
        }
    }
}

// ---------------- tf32 tensor-core GEMM: [M,K]@[K,128] ----------------
template<bool BIAS, bool ADDC, bool RELU, bool ACCUM>
__global__ void __launch_bounds__(256) gemm_tf32(
    const float* __restrict__ A, const float* __restrict__ W,
    const float* __restrict__ bias, const float* __restrict__ Cin,
    float* __restrict__ Cout, int M, int K)
{
    __shared__ float As[2][128][20];
    __shared__ float Bs[2][16][136];
    const int tid  = threadIdx.x;
    const int warp = tid >> 5, lane = tid & 31;
    const int wm = warp >> 1;
    const int wn = warp & 1;
    const int block_row = blockIdx.x * 128;
    const int lq = lane >> 2;
    const int lr = lane & 3;

    float acc[2][8][4];
    #pragma unroll
    for (int mt = 0; mt < 2; mt++)
        #pragma unroll
        for (int nt = 0; nt < 8; nt++)
            #pragma unroll
            for (int i = 0; i < 4; i++) acc[mt][nt][i] = 0.f;

    const int nk = K >> 4;
    {
        #pragma unroll
        for (int l = 0; l < 2; l++) {
            int idx = tid * 2 + l;
            int r = idx >> 2, c4 = (idx & 3) * 4;
            cpasync16(&As[0][r][c4], &A[(size_t)(block_row + r) * K + c4]);
        }
        #pragma unroll
        for (int l = 0; l < 2; l++) {
            int idx = tid * 2 + l;
            int r = idx >> 5, c4 = (idx & 31) * 4;
            cpasync16(&Bs[0][r][c4], &W[(size_t)r * CC + c4]);
        }
        CP_COMMIT();
    }

    for (int kk = 0; kk < nk; kk++) {
        int st = kk & 1;
        if (kk + 1 < nk) {
            int ns = st ^ 1, k0 = (kk + 1) * 16;
            #pragma unroll
            for (int l = 0; l < 2; l++) {
                int idx = tid * 2 + l;
                int r = idx >> 2, c4 = (idx & 3) * 4;
                cpasync16(&As[ns][r][c4], &A[(size_t)(block_row + r) * K + k0 + c4]);
            }
            #pragma unroll
            for (int l = 0; l < 2; l++) {
                int idx = tid * 2 + l;
                int r = idx >> 5, c4 = (idx & 31) * 4;
                cpasync16(&Bs[ns][r][c4], &W[(size_t)(k0 + r) * CC + c4]);
            }
            CP_COMMIT();
            CP_WAIT(1);
        } else {
            CP_WAIT(0);
        }
        __syncthreads();

        #pragma unroll
        for (int ks = 0; ks < 2; ks++) {
            const int k0 = ks * 8;
            uint32_t af[2][4], bf[8][2];
            const int arow0 = wm * 32 + lq;
            #pragma unroll
            for (int mt = 0; mt < 2; mt++) {
                int r = arow0 + mt * 16;
                af[mt][0] = f2tf(As[st][r    ][k0 + lr    ]);
                af[mt][1] = f2tf(As[st][r + 8][k0 + lr    ]);
                af[mt][2] = f2tf(As[st][r    ][k0 + lr + 4]);
                af[mt][3] = f2tf(As[st][r + 8][k0 + lr + 4]);
            }
            #pragma unroll
            for (int nt = 0; nt < 8; nt++) {
                int col = wn * 64 + nt * 8 + lq;
                bf[nt][0] = f2tf(Bs[st][k0 + lr    ][col]);
                bf[nt][1] = f2tf(Bs[st][k0 + lr + 4][col]);
            }
            #pragma unroll
            for (int mt = 0; mt < 2; mt++)
                #pragma unroll
                for (int nt = 0; nt < 8; nt++)
                    mma_tf32(acc[mt][nt], af[mt], bf[nt]);
        }
        __syncthreads();
    }

    #pragma unroll
    for (int mt = 0; mt < 2; mt++) {
        #pragma unroll
        for (int half = 0; half < 2; half++) {
            int row = block_row + wm * 32 + mt * 16 + lq + half * 8;
            #pragma unroll
            for (int nt = 0; nt < 8; nt++) {
                int col = wn * 64 + nt * 8 + lr * 2;
                float v0 = acc[mt][nt][half * 2 + 0];
                float v1 = acc[mt][nt][half * 2 + 1];
                if (BIAS) { v0 += bias[col]; v1 += bias[col + 1]; }
                if (ADDC) {
                    float2 c = *(const float2*)&Cin[(size_t)row * CC + col];
                    v0 += c.x; v1 += c.y;
                }
                if (RELU) { v0 = fmaxf(v0, 0.f); v1 = fmaxf(v1, 0.f); }
                if (ACCUM) {
                    float2 o = *(const float2*)&Cout[(size_t)row * CC + col];
                    v0 += o.x; v1 += o.y;
                }
                *(float2*)&Cout[(size_t)row * CC + col] = make_float2(v0, v1);
            }
        }
    }
}

// ---------------- tensor-core EdgeConv (batched, compacted list) ----------------
// dyn smem: W2s[128][136] u32 tf32 | Zs[32][132] u32 tf32 | b2s[128] f32 | spair[32] int2
#define W2S_STRIDE 136
#define ZS_STRIDE  132
#define SMEM_W2S_WORDS (128*W2S_STRIDE)          // 17408 words
#define SMEM_ZS_WORDS  (32*ZS_STRIDE)            // 4224 words
#define SMEM_CONV_BYTES ((SMEM_W2S_WORDS + SMEM_ZS_WORDS + 128 + 64 + 16) * 4)

__global__ void __launch_bounds__(256) conv_tc(
    const int2* __restrict__ list, const int* __restrict__ cntp,
    const float* __restrict__ W2, const float* __restrict__ b2,
    const float* __restrict__ P, const float* __restrict__ Q,
    float* __restrict__ out)
{
    extern __shared__ uint32_t dsm[];
    uint32_t* W2s  = dsm;
    uint32_t* Zs   = dsm + SMEM_W2S_WORDS;
    float*    b2s  = (float*)(dsm + SMEM_W2S_WORDS + SMEM_ZS_WORDS);
    int2*     spair= (int2*)(b2s + 128);

    const int tid  = threadIdx.x;
    const int warp = tid >> 5, lane = tid & 31;
    const int lq = lane >> 2, lr = lane & 3;
    const int wr = warp >> 2;            // 0..1 : 16 rows
    const int wc = warp & 3;             // 0..3 : 32 cols

    // stage W2 (tf32) + b2
    for (int i = tid; i < CC*CC; i += 256)
        W2s[(i >> 7) * W2S_STRIDE + (i & 127)] = f2tf(W2[i]);
    if (tid < 128) b2s[tid] = b2[tid];

    const int n = *cntp;
    const float4* P4 = (const float4*)P;
    const float4* Q4 = (const float4*)Q;

    for (int batch = blockIdx.x; batch * 32 < n; batch += gridDim.x) {
        const int base = batch * 32;
        const int m = min(32, n - base);
        __syncthreads();                  // smem free (also covers W2 staging, 1st iter)
        if (tid < 32)
            spair[tid] = (tid < m) ? list[base + tid] : make_int2(0, 0);
        __syncthreads();

        // gather Z = tf32(relu(P[dst] + Q[src])), 8 threads per edge
        {
            int e = tid >> 3, part = tid & 7;
            int2 sd = spair[e];
            uint32_t* zrow = &Zs[e * ZS_STRIDE + part * 16];
            if (e < m) {
                const float4* pr = &P4[(size_t)sd.y * 32 + part * 4];
                const float4* qr = &Q4[(size_t)sd.x * 32 + part * 4];
                #pragma unroll
                for (int j = 0; j < 4; j++) {
                    float4 p = __ldg(&pr[j]);
                    float4 q = __ldg(&qr[j]);
                    uint4 z;
                    z.x = f2tf(fmaxf(p.x + q.x, 0.f));
                    z.y = f2tf(fmaxf(p.y + q.y, 0.f));
                    z.z = f2tf(fmaxf(p.z + q.z, 0.f));
                    z.w = f2tf(fmaxf(p.w + q.w, 0.f));
                    *(uint4*)&zrow[j * 4] = z;
                }
            } else {
                #pragma unroll
                for (int j = 0; j < 4; j++)
                    *(uint4*)&zrow[j * 4] = make_uint4(0, 0, 0, 0);
            }
        }
        __syncthreads();

        // MMA: Z[32x128] @ W2[128x128]; warp tile 16x32
        float acc[4][4];
        #pragma unroll
        for (int nt = 0; nt < 4; nt++)
            #pragma unroll
            for (int i = 0; i < 4; i++) acc[nt][i] = 0.f;

        const int r0 = wr * 16 + lq;
        #pragma unroll
        for (int ks = 0; ks < 16; ks++) {
            uint32_t af[4];
            af[0] = Zs[ r0      * ZS_STRIDE + ks * 8 + lr    ];
            af[1] = Zs[(r0 + 8) * ZS_STRIDE + ks * 8 + lr    ];
            af[2] = Zs[ r0      * ZS_STRIDE + ks * 8 + lr + 4];
            af[3] = Zs[(r0 + 8) * ZS_STRIDE + ks * 8 + lr + 4];
            #pragma unroll
            for (int nt = 0; nt < 4; nt++) {
                uint32_t bf[2];
                int col = wc * 32 + nt * 8 + lq;
                bf[0] = W2s[(ks * 8 + lr    ) * W2S_STRIDE + col];
                bf[1] = W2s[(ks * 8 + lr + 4) * W2S_STRIDE + col];
                mma_tf32(acc[nt], af, bf);
            }
        }

        // epilogue: relu(acc + b2) -> atomicMax into out[dst]
        #pragma unroll
        for (int half = 0; half < 2; half++) {
            int rr = wr * 16 + lq + half * 8;
            if (rr < m) {
                int d = spair[rr].y;
                float* orow = &out[(size_t)d * CC];
                #pragma unroll
                for (int nt = 0; nt < 4; nt++) {
                    int col = wc * 32 + nt * 8 + lr * 2;
                    float v0 = fmaxf(acc[nt][half * 2 + 0] + b2s[col    ], 0.f);
                    float v1 = fmaxf(acc[nt][half * 2 + 1] + b2s[col + 1], 0.f);
                    atomicMax((int*)&orow[col    ], __float_as_int(v0));
                    atomicMax((int*)&orow[col + 1], __float_as_int(v1));
                }
            }
        }
    }
}

// ---------------- vectorized scatter kernels over compacted lists ----------------
// 32 threads per edge, float4 per thread
__global__ void __launch_bounds__(256) edge_vpa2() {
    const int n = g_ecnt[0];
    const int part = threadIdx.x & 31;
    const float4* X4 = (const float4*)g_x;
    for (int i = blockIdx.x * 8 + (threadIdx.x >> 5); i < n; i += gridDim.x * 8) {
        int2 sd = g_elist[0][i];
        float4 xs = __ldg(&X4[(size_t)sd.x * 32 + part]);
        float4 xd = __ldg(&X4[(size_t)sd.y * 32 + part]);
        float* orow = &g_xag[(size_t)sd.y * CC + part * 4];
        atomicMax((int*)&orow[0], __float_as_int(fmaxf(xs.x + xd.x, 0.f)));
        atomicMax((int*)&orow[1], __float_as_int(fmaxf(xs.y + xd.y, 0.f)));
        atomicMax((int*)&orow[2], __float_as_int(fmaxf(xs.z + xd.z, 0.f)));
        atomicMax((int*)&orow[3], __float_as_int(fmaxf(xs.w + xd.w, 0.f)));
    }
}
__global__ void __launch_bounds__(256) edge_acv2() {
    const int n = g_ecnt[2];
    const int part = threadIdx.x & 31;
    const float4* X4 = (const float4*)g_x;
    for (int i = blockIdx.x * 8 + (threadIdx.x >> 5); i < n; i += gridDim.x * 8) {
        int2 sd = g_elist[2][i];
        float w = g_ares[sd.x];
        float4 xs = __ldg(&X4[(size_t)sd.x * 32 + part]);
        float4 xd = __ldg(&X4[(size_t)sd.y * 32 + part]);
        float* orow = &g_xv2[(size_t)sd.y * CC + part * 4];
        atomicAdd(&orow[0], w * xs.x + xd.x);
        atomicAdd(&orow[1], w * xs.y + xd.y);
        atomicAdd(&orow[2], w * xs.z + xd.z);
        atomicAdd(&orow[3], w * xs.w + xd.w);
    }
}
__global__ void __launch_bounds__(256) edge_sage2(int li) {
    const int n = g_ecnt[li];
    const int part = threadIdx.x & 31;
    const float4* H4 = (const float4*)g_h;
    const int2* list = g_elist[li];
    for (int i = blockIdx.x * 8 + (threadIdx.x >> 5); i < n; i += gridDim.x * 8) {
        int2 sd = list[i];
        float4 hs = __ldg(&H4[(size_t)sd.x * 32 + part]);
        float* orow = &g_s[(size_t)sd.y * CC + part * 4];
        atomicAdd(&orow[0], hs.x);
        atomicAdd(&orow[1], hs.y);
        atomicAdd(&orow[2], hs.z);
        atomicAdd(&orow[3], hs.w);
        if (part == 0) atomicAdd(&g_cnt[sd.y], 1);
    }
}

// a_res = a @ fc_W + fc_b  (one warp per node)
__global__ void ares_kernel(const float* __restrict__ fcW, const float* __restrict__ fcb) {
    int warp = (blockIdx.x * blockDim.x + threadIdx.x) >> 5;
    int lane = threadIdx.x & 31;
    if (warp >= NNODE) return;
    const float* ap = &g_a[(size_t)warp * CC];
    float acc = 0.f;
    #pragma unroll
    for (int k = 0; k < 4; k++) acc += ap[lane + 32*k] * fcW[lane + 32*k];
    #pragma unroll
    for (int o = 16; o > 0; o >>= 1) acc += __shfl_xor_sync(0xffffffffu, acc, o);
    if (lane == 0) g_ares[warp] = acc + fcb[0];
}

__global__ void gather_out(float* __restrict__ out, int total, int step) {
    int i = blockIdx.x * blockDim.x + threadIdx.x;
    if (i >= total) return;
    int c = i & 127;
    int r = i >> 7;
    int t = r % TT, g = r / TT;
    int node = g * step + t;
    out[i] = g_xo[(size_t)node * CC + c];
}

// ---------------- host orchestration ----------------
static inline void* symv(const void* s) {
    void* p = nullptr;
    cudaGetSymbolAddress(&p, (const void*)s);
    return p;
}

extern "C" void kernel_launch(void* const* d_in, const int* in_sizes, int n_in,
                              void* d_out, int out_size) {
    const float* x_visual = (const float*)d_in[0];
    const float* x_audio  = (const float*)d_in[1];
    const float* W011 = (const float*)d_in[2];  const float* b011 = (const float*)d_in[3];
    const float* W012 = (const float*)d_in[4];  const float* b012 = (const float*)d_in[5];
    const float* ecW1[4] = {(const float*)d_in[6],  (const float*)d_in[10],
                            (const float*)d_in[14], (const float*)d_in[18]};
    const float* ecb1[4] = {(const float*)d_in[7],  (const float*)d_in[11],
                            (const float*)d_in[15], (const float*)d_in[19]};
    const float* ecW2[4] = {(const float*)d_in[8],  (const float*)d_in[12],
                            (const float*)d_in[16], (const float*)d_in[20]};
    const float* ecb2[4] = {(const float*)d_in[9],  (const float*)d_in[13],
                            (const float*)d_in[17], (const float*)d_in[21]};
    const float* Wl  = (const float*)d_in[22];
    const float* bl  = (const float*)d_in[23];
    const float* Wr  = (const float*)d_in[24];
    const float* fcW = (const float*)d_in[25];
    const float* fcb = (const float*)d_in[26];
    const int*   eidx = (const int*)d_in[27];
    const int*   attr = (const int*)d_in[28];
    const int E = in_sizes[27] / 2;
    const int* srcp = eidx;
    const int* dstp = eidx + E;

    float* px   = (float*)symv(g_x);    float* pxag = (float*)symv(g_xag);
    float* pP   = (float*)symv(g_P);    float* pQ   = (float*)symv(g_Q);
    float* pa   = (float*)symv(g_a);    float* pxv2 = (float*)symv(g_xv2);
    float* ph   = (float*)symv(g_h);    float* ps   = (float*)symv(g_s);
    float* ptmp = (float*)symv(g_tmp);  float* pxo  = (float*)symv(g_xo);
    float* pwp  = (float*)symv(g_WP);
    int*   pcnt = (int*)symv(g_cnt);
    int*   pecnt= (int*)symv(g_ecnt);
    int2*  plist= (int2*)symv(g_elist);

    const size_t NCB = (size_t)NC * sizeof(float);
    const int SCAT_GRID = 1184;     // 8*148
    const int CONV_GRID = 296;      // 2 blocks/SM at ~87KB smem

    cudaFuncSetAttribute(conv_tc, cudaFuncAttributeMaxDynamicSharedMemorySize, SMEM_CONV_BYTES);

    // edge compaction
    cudaMemsetAsync(pecnt, 0, 6 * sizeof(int));
    compact_edges<<<(E + 255)/256, 256>>>(srcp, dstp, attr, E);

    prep_wp<<<(4*CC*CC + 255)/256, 256>>>(ecW1[0], ecW1[1], ecW1[2], ecW1[3]);

    // input projections -> g_x
    gemm_tf32<true,false,false,false><<<MV/128, 256>>>(x_visual, W011, b011, nullptr, px, MV, FDIM);
    gemm_tf32<true,false,false,false><<<MA/128, 256>>>(x_audio,  W012, b012, nullptr, px + (size_t)MV*CC, MA, FDIM);

    // xa_g = relu(seg_max over vpa edges of x[dst]+x[src])
    cudaMemsetAsync(pxag, 0, NCB);
    edge_vpa2<<<SCAT_GRID, 256>>>();

    // convA: a = relu(EdgeConv(xa_g; attr==-2))
    gemm_tf32<true,false,false,false><<<NNODE/128, 256>>>(pxag, pwp,            ecb1[0], nullptr, pP, NNODE, CC);
    gemm_tf32<false,false,false,false><<<NNODE/128, 256>>>(pxag, ecW1[0]+CC*CC, nullptr, nullptr, pQ, NNODE, CC);
    cudaMemsetAsync(pa, 0, NCB);
    conv_tc<<<CONV_GRID, 256, SMEM_CONV_BYTES>>>(plist + 1*EMAX, pecnt + 1,
                                                 ecW2[0], ecb2[0], pP, pQ, pa);

    ares_kernel<<<NNODE/8, 256>>>(fcW, fcb);

    // xv2 = relu(segment_sum over attr==3 of a_res[src]*x[src] + x[dst])
    cudaMemsetAsync(pxv2, 0, NCB);
    edge_acv2<<<SCAT_GRID, 256>>>();
    relu_inplace<<<(NC + 255)/256, 256>>>(pxv2, NC);

    cudaMemsetAsync(pxo, 0, NCB);

    for (int b = 0; b < 3; b++) {
        const int ci = b + 1;        // conv params ec1/ec2/ec3
        const int li = b + 3;        // lists 3,4,5
        gemm_tf32<true,false,false,false><<<NNODE/128, 256>>>(pxv2, pwp + ci*CC*CC, ecb1[ci], nullptr, pP, NNODE, CC);
        gemm_tf32<false,false,false,false><<<NNODE/128, 256>>>(pxv2, ecW1[ci]+CC*CC, nullptr, nullptr, pQ, NNODE, CC);
        cudaMemsetAsync(ph, 0, NCB);
        conv_tc<<<CONV_GRID, 256, SMEM_CONV_BYTES>>>(plist + li*EMAX, pecnt + li,
                                                     ecW2[ci], ecb2[ci], pP, pQ, ph);
        cudaMemsetAsync(ps, 0, NCB);
        cudaMemsetAsync(pcnt, 0, NNODE * sizeof(int));
        edge_sage2<<<SCAT_GRID, 256>>>(li);
        mean_kernel<<<(NC + 255)/256, 256>>>(ps, pcnt, NC);
        gemm_tf32<true,false,false,false><<<NNODE/128, 256>>>(ps, Wl, bl, nullptr, ptmp, NNODE, CC);
        gemm_tf32<false,true,true,true><<<NNODE/128, 256>>>(ph, Wr, nullptr, ptmp, pxo, NNODE, CC);
    }

    int groups = out_size / (TT * CC);
    int step   = MV / groups;
    gather_out<<<(out_size + 255)/256, 256>>>((float*)d_out, out_size, step);
}

// round 7
// speedup vs baseline: 3.7020x; 1.0158x over previous
#include <cuda_runtime.h>
#include <cstdint>

// ---------------- fixed problem dims ----------------
#define NVIS   192
#define NAUD   64
#define TT     128
#define FDIM   1024
#define CC     128
#define MV     (NVIS*TT)      // 24576 visual nodes
#define MA     (NAUD*TT)      // 8192  audio nodes
#define NNODE  (MV+MA)        // 32768
#define NC     (NNODE*CC)     // 4194304
#define EMAX   262144

// ---------------- scratch (device globals; no allocs allowed) ----------------
__device__ float g_x   [NC];
__device__ float g_xag [NC];
__device__ float g_P   [NC];
__device__ float g_Q   [NC];
__device__ float g_a   [NC];
__device__ float g_xv2 [NC];
__device__ float g_h   [NC];
__device__ float g_s   [NC];
__device__ float g_xo  [NC];
__device__ float g_ares[NNODE];
__device__ int   g_cnt [NNODE];
__device__ float g_WP  [4*CC*CC];
__device__ int2  g_elist[6][EMAX];   // 0:vpa(-3) 1:audio(-2) 2:acv(3) 3:[0,1] 4:[-1,0] 5:[-1,1]
__device__ int   g_ecnt[6];

// ---------------- small helpers ----------------
__device__ __forceinline__ uint32_t f2tf(float x) {
    uint32_t r;
    asm("cvt.rna.tf32.f32 %0, %1;\n" : "=r"(r) : "f"(x));
    return r;
}
__device__ __forceinline__ void cpasync16(void* dst, const void* src) {
    uint32_t d = (uint32_t)__cvta_generic_to_shared(dst);
    asm volatile("cp.async.cg.shared.global [%0], [%1], 16;\n" :: "r"(d), "l"(src));
}
#define CP_COMMIT()  asm volatile("cp.async.commit_group;\n")
#define CP_WAIT(n)   asm volatile("cp.async.wait_group %0;\n" :: "n"(n))

__device__ __forceinline__ void mma_tf32(float* c, const uint32_t* a, const uint32_t* b) {
    asm volatile(
        "mma.sync.aligned.m16n8k8.row.col.f32.tf32.tf32.f32 "
        "{%0,%1,%2,%3}, {%4,%5,%6,%7}, {%8,%9}, {%0,%1,%2,%3};\n"
        : "+f"(c[0]), "+f"(c[1]), "+f"(c[2]), "+f"(c[3])
        : "r"(a[0]), "r"(a[1]), "r"(a[2]), "r"(a[3]), "r"(b[0]), "r"(b[1]));
}

// ---------------- utility kernels ----------------
__global__ void relu_inplace(float* __restrict__ p, int n) {
    int i = blockIdx.x * blockDim.x + threadIdx.x;
    if (i < n) p[i] = fmaxf(p[i], 0.f);
}
__global__ void mean_kernel(float* __restrict__ s, const int* __restrict__ cnt, int n) {
    int i = blockIdx.x * blockDim.x + threadIdx.x;
    if (i < n) {
        int c = cnt[i >> 7];
        s[i] = s[i] / (float)(c > 1 ? c : 1);
    }
}
__global__ void prep_wp(const float* __restrict__ w0, const float* __restrict__ w1,
                        const float* __restrict__ w2, const float* __restrict__ w3) {
    int i = blockIdx.x * blockDim.x + threadIdx.x;
    if (i >= 4*CC*CC) return;
    int conv = i >> 14, j = i & 16383;
    const float* W = conv == 0 ? w0 : conv == 1 ? w1 : conv == 2 ? w2 : w3;
    g_WP[i] = W[j] - W[CC*CC + j];
}

// ---------------- edge compaction (warp-aggregated) ----------------
__global__ void compact_edges(const int* __restrict__ src, const int* __restrict__ dst,
                              const int* __restrict__ attr, int E) {
    int e = blockIdx.x * blockDim.x + threadIdx.x;
    if (e >= E) return;
    int a = attr[e];
    int2 sd = make_int2(src[e], dst[e]);
    bool pr[6];
    pr[0] = (a == -3);
    pr[1] = (a == -2);
    pr[2] = (a ==  3);
    pr[3] = (a >=  0) && (a <= 1);
    pr[4] = (a >= -1) && (a <= 0);
    pr[5] = (a >= -1) && (a <= 1);
    int lane = threadIdx.x & 31;
    #pragma unroll
    for (int i = 0; i < 6; i++) {
        unsigned mask = __ballot_sync(0xffffffffu, pr[i]);
        if (pr[i]) {
            int leader = __ffs(mask) - 1;
            int pos = 0;
            if (lane == leader) pos = atomicAdd(&g_ecnt[i], __popc(mask));
            pos = __shfl_sync(mask, pos, leader);
            int rank = __popc(mask & ((1u << lane) - 1));
            g_elist[i][pos + rank] = sd;
        }
    }
}

// ============= GEMM 1: split-K projection  C (+)= A[M,1024] @ W[1024,128] (+bias) =====
// BM=64 BN=128 BK=16, split-K over blockIdx.y (4 splits of K=256), atomicAdd epilogue.
__global__ void __launch_bounds__(256) gemm_splitk(
    const float* __restrict__ A, const float* __restrict__ W,
    const float* __restrict__ bias, float* __restrict__ Cout, int M)
{
    __shared__ float As[2][64][20];
    __shared__ float Bs[2][16][136];
    const int tid  = threadIdx.x;
    const int warp = tid >> 5, lane = tid & 31;
    const int wm = warp >> 2;              // 0..1 (32 rows)
    const int wn = warp & 3;               // 0..3 (32 cols)
    const int block_row = blockIdx.x * 64;
    const int ks = blockIdx.y;             // 0..3
    const int kbase = ks * 256;
    const int lq = lane >> 2, lr = lane & 3;

    float acc[2][4][4];
    #pragma unroll
    for (int mt = 0; mt < 2; mt++)
        #pragma unroll
        for (int nt = 0; nt < 4; nt++)
            #pragma unroll
            for (int i = 0; i < 4; i++) acc[mt][nt][i] = 0.f;

    const int nk = 16;   // 256/16
    {
        {
            int r = tid >> 2, c4 = (tid & 3) * 4;
            cpasync16(&As[0][r][c4], &A[(size_t)(block_row + r) * FDIM + kbase + c4]);
        }
        #pragma unroll
        for (int l = 0; l < 2; l++) {
            int idx = tid * 2 + l;
            int r = idx >> 5, c4 = (idx & 31) * 4;
            cpasync16(&Bs[0][r][c4], &W[(size_t)(kbase + r) * CC + c4]);
        }
        CP_COMMIT();
    }

    for (int kk = 0; kk < nk; kk++) {
        int st = kk & 1;
        if (kk + 1 < nk) {
            int ns = st ^ 1, k0 = kbase + (kk + 1) * 16;
            {
                int r = tid >> 2, c4 = (tid & 3) * 4;
                cpasync16(&As[ns][r][c4], &A[(size_t)(block_row + r) * FDIM + k0 + c4]);
            }
            #pragma unroll
            for (int l = 0; l < 2; l++) {
                int idx = tid * 2 + l;
                int r = idx >> 5, c4 = (idx & 31) * 4;
                cpasync16(&Bs[ns][r][c4], &W[(size_t)(k0 + r) * CC + c4]);
            }
            CP_COMMIT();
            CP_WAIT(1);
        } else {
            CP_WAIT(0);
        }
        __syncthreads();

        #pragma unroll
        for (int kss = 0; kss < 2; kss++) {
            const int k0 = kss * 8;
            uint32_t af[2][4], bf[4][2];
            const int arow0 = wm * 32 + lq;
            #pragma unroll
            for (int mt = 0; mt < 2; mt++) {
                int r = arow0 + mt * 16;
                af[mt][0] = f2tf(As[st][r    ][k0 + lr    ]);
                af[mt][1] = f2tf(As[st][r + 8][k0 + lr    ]);
                af[mt][2] = f2tf(As[st][r    ][k0 + lr + 4]);
                af[mt][3] = f2tf(As[st][r + 8][k0 + lr + 4]);
            }
            #pragma unroll
            for (int nt = 0; nt < 4; nt++) {
                int col = wn * 32 + nt * 8 + lq;
                bf[nt][0] = f2tf(Bs[st][k0 + lr    ][col]);
                bf[nt][1] = f2tf(Bs[st][k0 + lr + 4][col]);
            }
            #pragma unroll
            for (int mt = 0; mt < 2; mt++)
                #pragma unroll
                for (int nt = 0; nt < 4; nt++)
                    mma_tf32(acc[mt][nt], af[mt], bf[nt]);
        }
        __syncthreads();
    }

    #pragma unroll
    for (int mt = 0; mt < 2; mt++) {
        #pragma unroll
        for (int half = 0; half < 2; half++) {
            int row = block_row + wm * 32 + mt * 16 + lq + half * 8;
            #pragma unroll
            for (int nt = 0; nt < 4; nt++) {
                int col = wn * 32 + nt * 8 + lr * 2;
                float v0 = acc[mt][nt][half * 2 + 0];
                float v1 = acc[mt][nt][half * 2 + 1];
                if (ks == 0) { v0 += bias[col]; v1 += bias[col + 1]; }
                atomicAdd(&Cout[(size_t)row * CC + col    ], v0);
                atomicAdd(&Cout[(size_t)row * CC + col + 1], v1);
            }
        }
    }
}

// ===== GEMM 2: dual-weight  P = A@W1+b1 ; Q = A@W2  (shared A, BN=256) ==============
// BM=64, 256 threads, 8 warps: wm 0..1 (32 rows), wn 0..3 (64 cols of 256-concat).
__global__ void __launch_bounds__(256) gemm_dual(
    const float* __restrict__ A,
    const float* __restrict__ W1, const float* __restrict__ b1,
    const float* __restrict__ W2,
    float* __restrict__ C1, float* __restrict__ C2)
{
    __shared__ float As[2][64][20];
    __shared__ float Bs[2][16][264];
    const int tid  = threadIdx.x;
    const int warp = tid >> 5, lane = tid & 31;
    const int wm = warp >> 2;              // 0..1
    const int wn = warp & 3;               // 0..3 (64 cols each in 256 space)
    const int block_row = blockIdx.x * 64;
    const int lq = lane >> 2, lr = lane & 3;

    float acc[2][8][4];
    #pragma unroll
    for (int mt = 0; mt < 2; mt++)
        #pragma unroll
        for (int nt = 0; nt < 8; nt++)
            #pragma unroll
            for (int i = 0; i < 4; i++) acc[mt][nt][i] = 0.f;

    const int nk = 8;      // K=128
    {
        {
            int r = tid >> 2, c4 = (tid & 3) * 4;
            cpasync16(&As[0][r][c4], &A[(size_t)(block_row + r) * CC + c4]);
        }
        #pragma unroll
        for (int l = 0; l < 4; l++) {
            int idx = tid * 4 + l;
            int r = idx >> 6, c = (idx & 63) * 4;
            const float* s = (c < 128) ? &W1[(size_t)r * CC + c] : &W2[(size_t)r * CC + (c - 128)];
            cpasync16(&Bs[0][r][c], s);
        }
        CP_COMMIT();
    }

    for (int kk = 0; kk < nk; kk++) {
        int st = kk & 1;
        if (kk + 1 < nk) {
            int ns = st ^ 1, k0 = (kk + 1) * 16;
            {
                int r = tid >> 2, c4 = (tid & 3) * 4;
                cpasync16(&As[ns][r][c4], &A[(size_t)(block_row + r) * CC + k0 + c4]);
            }
            #pragma unroll
            for (int l = 0; l < 4; l++) {
                int idx = tid * 4 + l;
                int r = idx >> 6, c = (idx & 63) * 4;
                const float* s = (c < 128) ? &W1[(size_t)(k0 + r) * CC + c]
                                           : &W2[(size_t)(k0 + r) * CC + (c - 128)];
                cpasync16(&Bs[ns][r][c], s);
            }
            CP_COMMIT();
            CP_WAIT(1);
        } else {
            CP_WAIT(0);
        }
        __syncthreads();

        #pragma unroll
        for (int kss = 0; kss < 2; kss++) {
            const int k0 = kss * 8;
            uint32_t af[2][4], bf[8][2];
            const int arow0 = wm * 32 + lq;
            #pragma unroll
            for (int mt = 0; mt < 2; mt++) {
                int r = arow0 + mt * 16;
                af[mt][0] = f2tf(As[st][r    ][k0 + lr    ]);
                af[mt][1] = f2tf(As[st][r + 8][k0 + lr    ]);
                af[mt][2] = f2tf(As[st][r    ][k0 + lr + 4]);
                af[mt][3] = f2tf(As[st][r + 8][k0 + lr + 4]);
            }
            #pragma unroll
            for (int nt = 0; nt < 8; nt++) {
                int col = wn * 64 + nt * 8 + lq;
                bf[nt][0] = f2tf(Bs[st][k0 + lr    ][col]);
                bf[nt][1] = f2tf(Bs[st][k0 + lr + 4][col]);
            }
            #pragma unroll
            for (int mt = 0; mt < 2; mt++)
                #pragma unroll
                for (int nt = 0; nt < 8; nt++)
                    mma_tf32(acc[mt][nt], af[mt], bf[nt]);
        }
        __syncthreads();
    }

    const bool first = (wn < 2);
    float* Cout = first ? C1 : C2;
    const int colbase = (first ? wn : (wn - 2)) * 64;
    #pragma unroll
    for (int mt = 0; mt < 2; mt++) {
        #pragma unroll
        for (int half = 0; half < 2; half++) {
            int row = block_row + wm * 32 + mt * 16 + lq + half * 8;
            #pragma unroll
            for (int nt = 0; nt < 8; nt++) {
                int col = colbase + nt * 8 + lr * 2;
                float v0 = acc[mt][nt][half * 2 + 0];
                float v1 = acc[mt][nt][half * 2 + 1];
                if (first) { v0 += b1[col]; v1 += b1[col + 1]; }
                *(float2*)&Cout[(size_t)row * CC + col] = make_float2(v0, v1);
            }
        }
    }
}

// ===== GEMM 3: fused SAGE  xo += relu( A1@W1 + bias + A2@W2 )  (concat-K=256) =======
// BM=128 BN=128, 256 threads, same fragment mapping as before.
__global__ void __launch_bounds__(256) gemm_sage(
    const float* __restrict__ A1, const float* __restrict__ W1,
    const float* __restrict__ bias,
    const float* __restrict__ A2, const float* __restrict__ W2,
    float* __restrict__ Cout)
{
    __shared__ float As[2][128][20];
    __shared__ float Bs[2][16][136];
    const int tid  = threadIdx.x;
    const int warp = tid >> 5, lane = tid & 31;
    const int wm = warp >> 1;
    const int wn = warp & 1;
    const int block_row = blockIdx.x * 128;
    const int lq = lane >> 2, lr = lane & 3;

    float acc[2][8][4];
    #pragma unroll
    for (int mt = 0; mt < 2; mt++)
        #pragma unroll
        for (int nt = 0; nt < 8; nt++)
            #pragma unroll
            for (int i = 0; i < 4; i++) acc[mt][nt][i] = 0.f;

    const int nk = 16;     // K=256 concat
    {
        #pragma unroll
        for (int l = 0; l < 2; l++) {
            int idx = tid * 2 + l;
            int r = idx >> 2, c4 = (idx & 3) * 4;
            cpasync16(&As[0][r][c4], &A1[(size_t)(block_row + r) * CC + c4]);
        }
        #pragma unroll
        for (int l = 0; l < 2; l++) {
            int idx = tid * 2 + l;
            int r = idx >> 5, c4 = (idx & 31) * 4;
            cpasync16(&Bs[0][r][c4], &W1[(size_t)r * CC + c4]);
        }
        CP_COMMIT();
    }

    for (int kk = 0; kk < nk; kk++) {
        int st = kk & 1;
        if (kk + 1 < nk) {
            int ns = st ^ 1;
            int kn = kk + 1;
            const float* Asrc = (kn < 8) ? A1 : A2;
            const float* Wsrc = (kn < 8) ? W1 : W2;
            int k0 = (kn & 7) * 16;
            #pragma unroll
            for (int l = 0; l < 2; l++) {
                int idx = tid * 2 + l;
                int r = idx >> 2, c4 = (idx & 3) * 4;
                cpasync16(&As[ns][r][c4], &Asrc[(size_t)(block_row + r) * CC + k0 + c4]);
            }
            #pragma unroll
            for (int l = 0; l < 2; l++) {
                int idx = tid * 2 + l;
                int r = idx >> 5, c4 = (idx & 31) * 4;
                cpasync16(&Bs[ns][r][c4], &Wsrc[(size_t)(k0 + r) * CC + c4]);
            }
            CP_COMMIT();
            CP_WAIT(1);
        } else {
            CP_WAIT(0);
        }
        __syncthreads();

        #pragma unroll
        for (int kss = 0; kss < 2; kss++) {
            const int k0 = kss * 8;
            uint32_t af[2][4], bf[8][2];
            const int arow0 = wm * 32 + lq;
            #pragma unroll
            for (int mt = 0; mt < 2; mt++) {
                int r = arow0 + mt * 16;
                af[mt][0] = f2tf(As[st][r    ][k0 + lr    ]);
                af[mt][1] = f2tf(As[st][r + 8][k0 + lr    ]);
                af[mt][2] = f2tf(As[st][r    ][k0 + lr + 4]);
                af[mt][3] = f2tf(As[st][r + 8][k0 + lr + 4]);
            }
            #pragma unroll
            for (int nt = 0; nt < 8; nt++) {
                int col = wn * 64 + nt * 8 + lq;
                bf[nt][0] = f2tf(Bs[st][k0 + lr    ][col]);
                bf[nt][1] = f2tf(Bs[st][k0 + lr + 4][col]);
            }
            #pragma unroll
            for (int mt = 0; mt < 2; mt++)
                #pragma unroll
                for (int nt = 0; nt < 8; nt++)
                    mma_tf32(acc[mt][nt], af[mt], bf[nt]);
        }
        __syncthreads();
    }

    #pragma unroll
    for (int mt = 0; mt < 2; mt++) {
        #pragma unroll
        for (int half = 0; half < 2; half++) {
            int row = block_row + wm * 32 + mt * 16 + lq + half * 8;
            #pragma unroll
            for (int nt = 0; nt < 8; nt++) {
                int col = wn * 64 + nt * 8 + lr * 2;
                float v0 = acc[mt][nt][half * 2 + 0] + bias[col];
                float v1 = acc[mt][nt][half * 2 + 1] + bias[col + 1];
                v0 = fmaxf(v0, 0.f);
                v1 = fmaxf(v1, 0.f);
                float2 o = *(const float2*)&Cout[(size_t)row * CC + col];
                *(float2*)&Cout[(size_t)row * CC + col] = make_float2(v0 + o.x, v1 + o.y);
            }
        }
    }
}

// ---------------- tensor-core EdgeConv (batched, compacted list) ----------------
#define W2S_STRIDE 136
#define ZS_STRIDE  132
#define SMEM_W2S_WORDS (128*W2S_STRIDE)
#define SMEM_ZS_WORDS  (32*ZS_STRIDE)
#define SMEM_CONV_BYTES ((SMEM_W2S_WORDS + SMEM_ZS_WORDS + 128 + 64 + 16) * 4)

__global__ void __launch_bounds__(256) conv_tc(
    const int2* __restrict__ list, const int* __restrict__ cntp,
    const float* __restrict__ W2, const float* __restrict__ b2,
    const float* __restrict__ P, const float* __restrict__ Q,
    float* __restrict__ out)
{
    extern __shared__ uint32_t dsm[];
    uint32_t* W2s  = dsm;
    uint32_t* Zs   = dsm + SMEM_W2S_WORDS;
    float*    b2s  = (float*)(dsm + SMEM_W2S_WORDS + SMEM_ZS_WORDS);
    int2*     spair= (int2*)(b2s + 128);

    const int tid  = threadIdx.x;
    const int warp = tid >> 5, lane = tid & 31;
    const int lq = lane >> 2, lr = lane & 3;
    const int wr = warp >> 2;
    const int wc = warp & 3;

    for (int i = tid; i < CC*CC; i += 256)
        W2s[(i >> 7) * W2S_STRIDE + (i & 127)] = f2tf(W2[i]);
    if (tid < 128) b2s[tid] = b2[tid];

    const int n = *cntp;
    const float4* P4 = (const float4*)P;
    const float4* Q4 = (const float4*)Q;

    for (int batch = blockIdx.x; batch * 32 < n; batch += gridDim.x) {
        const int base = batch * 32;
        const int m = min(32, n - base);
        __syncthreads();
        if (tid < 32)
            spair[tid] = (tid < m) ? list[base + tid] : make_int2(0, 0);
        __syncthreads();

        {
            int e = tid >> 3, part = tid & 7;
            int2 sd = spair[e];
            uint32_t* zrow = &Zs[e * ZS_STRIDE + part * 16];
            if (e < m) {
                const float4* pr = &P4[(size_t)sd.y * 32 + part * 4];
                const float4* qr = &Q4[(size_t)sd.x * 32 + part * 4];
                #pragma unroll
                for (int j = 0; j < 4; j++) {
                    float4 p = __ldg(&pr[j]);
                    float4 q = __ldg(&qr[j]);
                    uint4 z;
                    z.x = f2tf(fmaxf(p.x + q.x, 0.f));
                    z.y = f2tf(fmaxf(p.y + q.y, 0.f));
                    z.z = f2tf(fmaxf(p.z + q.z, 0.f));
                    z.w = f2tf(fmaxf(p.w + q.w, 0.f));
                    *(uint4*)&zrow[j * 4] = z;
                }
            } else {
                #pragma unroll
                for (int j = 0; j < 4; j++)
                    *(uint4*)&zrow[j * 4] = make_uint4(0, 0, 0, 0);
            }
        }
        __syncthreads();

        float acc[4][4];
        #pragma unroll
        for (int nt = 0; nt < 4; nt++)
            #pragma unroll
            for (int i = 0; i < 4; i++) acc[nt][i] = 0.f;

        const int r0 = wr * 16 + lq;
        #pragma unroll
        for (int ks = 0; ks < 16; ks++) {
            uint32_t af[4];
            af[0] = Zs[ r0      * ZS_STRIDE + ks * 8 + lr    ];
            af[1] = Zs[(r0 + 8) * ZS_STRIDE + ks * 8 + lr    ];
            af[2] = Zs[ r0      * ZS_STRIDE + ks * 8 + lr + 4];
            af[3] = Zs[(r0 + 8) * ZS_STRIDE + ks * 8 + lr + 4];
            #pragma unroll
            for (int nt = 0; nt < 4; nt++) {
                uint32_t bf[2];
                int col = wc * 32 + nt * 8 + lq;
                bf[0] = W2s[(ks * 8 + lr    ) * W2S_STRIDE + col];
                bf[1] = W2s[(ks * 8 + lr + 4) * W2S_STRIDE + col];
                mma_tf32(acc[nt], af, bf);
            }
        }

        #pragma unroll
        for (int half = 0; half < 2; half++) {
            int rr = wr * 16 + lq + half * 8;
            if (rr < m) {
                int d = spair[rr].y;
                float* orow = &out[(size_t)d * CC];
                #pragma unroll
                for (int nt = 0; nt < 4; nt++) {
                    int col = wc * 32 + nt * 8 + lr * 2;
                    float v0 = fmaxf(acc[nt][half * 2 + 0] + b2s[col    ], 0.f);
                    float v1 = fmaxf(acc[nt][half * 2 + 1] + b2s[col + 1], 0.f);
                    atomicMax((int*)&orow[col    ], __float_as_int(v0));
                    atomicMax((int*)&orow[col + 1], __float_as_int(v1));
                }
            }
        }
    }
}

// ---------------- vectorized scatter kernels over compacted lists ----------------
__global__ void __launch_bounds__(256) edge_vpa2() {
    const int n = g_ecnt[0];
    const int part = threadIdx.x & 31;
    const float4* X4 = (const float4*)g_x;
    for (int i = blockIdx.x * 8 + (threadIdx.x >> 5); i < n; i += gridDim.x * 8) {
        int2 sd = g_elist[0][i];
        float4 xs = __ldg(&X4[(size_t)sd.x * 32 + part]);
        float4 xd = __ldg(&X4[(size_t)sd.y * 32 + part]);
        float* orow = &g_xag[(size_t)sd.y * CC + part * 4];
        atomicMax((int*)&orow[0], __float_as_int(fmaxf(xs.x + xd.x, 0.f)));
        atomicMax((int*)&orow[1], __float_as_int(fmaxf(xs.y + xd.y, 0.f)));
        atomicMax((int*)&orow[2], __float_as_int(fmaxf(xs.z + xd.z, 0.f)));
        atomicMax((int*)&orow[3], __float_as_int(fmaxf(xs.w + xd.w, 0.f)));
    }
}
__global__ void __launch_bounds__(256) edge_acv2() {
    const int n = g_ecnt[2];
    const int part = threadIdx.x & 31;
    const float4* X4 = (const float4*)g_x;
    for (int i = blockIdx.x * 8 + (threadIdx.x >> 5); i < n; i += gridDim.x * 8) {
        int2 sd = g_elist[2][i];
        float w = g_ares[sd.x];
        float4 xs = __ldg(&X4[(size_t)sd.x * 32 + part]);
        float4 xd = __ldg(&X4[(size_t)sd.y * 32 + part]);
        float* orow = &g_xv2[(size_t)sd.y * CC + part * 4];
        atomicAdd(&orow[0], w * xs.x + xd.x);
        atomicAdd(&orow[1], w * xs.y + xd.y);
        atomicAdd(&orow[2], w * xs.z + xd.z);
        atomicAdd(&orow[3], w * xs.w + xd.w);
    }
}
__global__ void __launch_bounds__(256) edge_sage2(int li) {
    const int n = g_ecnt[li];
    const int part = threadIdx.x & 31;
    const float4* H4 = (const float4*)g_h;
    const int2* list = g_elist[li];
    for (int i = blockIdx.x * 8 + (threadIdx.x >> 5); i < n; i += gridDim.x * 8) {
        int2 sd = list[i];
        float4 hs = __ldg(&H4[(size_t)sd.x * 32 + part]);
        float* orow = &g_s[(size_t)sd.y * CC + part * 4];
        atomicAdd(&orow[0], hs.x);
        atomicAdd(&orow[1], hs.y);
        atomicAdd(&orow[2], hs.z);
        atomicAdd(&orow[3], hs.w);
        if (part == 0) atomicAdd(&g_cnt[sd.y], 1);
    }
}

// a_res = a @ fc_W + fc_b
__global__ void ares_kernel(const float* __restrict__ fcW, const float* __restrict__ fcb) {
    int warp = (blockIdx.x * blockDim.x + threadIdx.x) >> 5;
    int lane = threadIdx.x & 31;
    if (warp >= NNODE) return;
    const float* ap = &g_a[(size_t)warp * CC];
    float acc = 0.f;
    #pragma unroll
    for (int k = 0; k < 4; k++) acc += ap[lane + 32*k] * fcW[lane + 32*k];
    #pragma unroll
    for (int o = 16; o > 0; o >>= 1) acc += __shfl_xor_sync(0xffffffffu, acc, o);
    if (lane == 0) g_ares[warp] = acc + fcb[0];
}

__global__ void gather_out(float* __restrict__ out, int total, int step) {
    int i = blockIdx.x * blockDim.x + threadIdx.x;
    if (i >= total) return;
    int c = i & 127;
    int r = i >> 7;
    int t = r % TT, g = r / TT;
    int node = g * step + t;
    out[i] = g_xo[(size_t)node * CC + c];
}

// ---------------- host orchestration ----------------
static inline void* symv(const void* s) {
    void* p = nullptr;
    cudaGetSymbolAddress(&p, (const void*)s);
    return p;
}

extern "C" void kernel_launch(void* const* d_in, const int* in_sizes, int n_in,
                              void* d_out, int out_size) {
    const float* x_visual = (const float*)d_in[0];
    const float* x_audio  = (const float*)d_in[1];
    const float* W011 = (const float*)d_in[2];  const float* b011 = (const float*)d_in[3];
    const float* W012 = (const float*)d_in[4];  const float* b012 = (const float*)d_in[5];
    const float* ecW1[4] = {(const float*)d_in[6],  (const float*)d_in[10],
                            (const float*)d_in[14], (const float*)d_in[18]};
    const float* ecb1[4] = {(const float*)d_in[7],  (const float*)d_in[11],
                            (const float*)d_in[15], (const float*)d_in[19]};
    const float* ecW2[4] = {(const float*)d_in[8],  (const float*)d_in[12],
                            (const float*)d_in[16], (const float*)d_in[20]};
    const float* ecb2[4] = {(const float*)d_in[9],  (const float*)d_in[13],
                            (const float*)d_in[17], (const float*)d_in[21]};
    const float* Wl  = (const float*)d_in[22];
    const float* bl  = (const float*)d_in[23];
    const float* Wr  = (const float*)d_in[24];
    const float* fcW = (const float*)d_in[25];
    const float* fcb = (const float*)d_in[26];
    const int*   eidx = (const int*)d_in[27];
    const int*   attr = (const int*)d_in[28];
    const int E = in_sizes[27] / 2;
    const int* srcp = eidx;
    const int* dstp = eidx + E;

    float* px   = (float*)symv(g_x);    float* pxag = (float*)symv(g_xag);
    float* pP   = (float*)symv(g_P);    float* pQ   = (float*)symv(g_Q);
    float* pa   = (float*)symv(g_a);    float* pxv2 = (float*)symv(g_xv2);
    float* ph   = (float*)symv(g_h);    float* ps   = (float*)symv(g_s);
    float* pxo  = (float*)symv(g_xo);
    float* pwp  = (float*)symv(g_WP);
    int*   pcnt = (int*)symv(g_cnt);
    int*   pecnt= (int*)symv(g_ecnt);
    int2*  plist= (int2*)symv(g_elist);

    const size_t NCB = (size_t)NC * sizeof(float);
    const int SCAT_GRID = 1184;
    const int CONV_GRID = 296;

    cudaFuncSetAttribute(conv_tc, cudaFuncAttributeMaxDynamicSharedMemorySize, SMEM_CONV_BYTES);

    // edge compaction
    cudaMemsetAsync(pecnt, 0, 6 * sizeof(int));
    compact_edges<<<(E + 255)/256, 256>>>(srcp, dstp, attr, E);

    prep_wp<<<(4*CC*CC + 255)/256, 256>>>(ecW1[0], ecW1[1], ecW1[2], ecW1[3]);

    // input projections -> g_x (split-K, atomic accumulate)
    cudaMemsetAsync(px, 0, NCB);
    gemm_splitk<<<dim3(MV/64, 4), 256>>>(x_visual, W011, b011, px, MV);
    gemm_splitk<<<dim3(MA/64, 4), 256>>>(x_audio,  W012, b012, px + (size_t)MV*CC, MA);

    // xa_g = relu(seg_max over vpa edges of x[dst]+x[src])
    cudaMemsetAsync(pxag, 0, NCB);
    edge_vpa2<<<SCAT_GRID, 256>>>();

    // convA: a = relu(EdgeConv(xa_g; attr==-2))
    gemm_dual<<<NNODE/64, 256>>>(pxag, pwp, ecb1[0], ecW1[0]+CC*CC, pP, pQ);
    cudaMemsetAsync(pa, 0, NCB);
    conv_tc<<<CONV_GRID, 256, SMEM_CONV_BYTES>>>(plist + 1*EMAX, pecnt + 1,
                                                 ecW2[0], ecb2[0], pP, pQ, pa);

    ares_kernel<<<NNODE/8, 256>>>(fcW, fcb);

    // xv2 = relu(segment_sum over attr==3 of a_res[src]*x[src] + x[dst])
    cudaMemsetAsync(pxv2, 0, NCB);
    edge_acv2<<<SCAT_GRID, 256>>>();
    relu_inplace<<<(NC + 255)/256, 256>>>(pxv2, NC);

    cudaMemsetAsync(pxo, 0, NCB);

    for (int b = 0; b < 3; b++) {
        const int ci = b + 1;        // conv params ec1/ec2/ec3
        const int li = b + 3;        // lists 3,4,5
        gemm_dual<<<NNODE/64, 256>>>(pxv2, pwp + ci*CC*CC, ecb1[ci], ecW1[ci]+CC*CC, pP, pQ);
        cudaMemsetAsync(ph, 0, NCB);
        conv_tc<<<CONV_GRID, 256, SMEM_CONV_BYTES>>>(plist + li*EMAX, pecnt + li,
                                                     ecW2[ci], ecb2[ci], pP, pQ, ph);
        cudaMemsetAsync(ps, 0, NCB);
        cudaMemsetAsync(pcnt, 0, NNODE * sizeof(int));
        edge_sage2<<<SCAT_GRID, 256>>>(li);
        mean_kernel<<<(NC + 255)/256, 256>>>(ps, pcnt, NC);
        // xo += relu( mean@Wl + bl + h@Wr )   (concat-K fused)
        gemm_sage<<<NNODE/128, 256>>>(ps, Wl, bl, ph, Wr, pxo);
    }

    int groups = out_size / (TT * CC);
    int step   = MV / groups;
    gather_out<<<(out_size + 255)/256, 256>>>((float*)d_out, out_size, step);
}

// round 9
// speedup vs baseline: 4.0556x; 1.0955x over previous
#include <cuda_runtime.h>
#include <cstdint>

// ---------------- fixed problem dims ----------------
#define NVIS   192
#define NAUD   64
#define TT     128
#define FDIM   1024
#define CC     128
#define MV     (NVIS*TT)      // 24576 visual nodes
#define MA     (NAUD*TT)      // 8192  audio nodes
#define NNODE  (MV+MA)        // 32768
#define NC     (NNODE*CC)     // 4194304
#define EMAX   262144

// ---------------- scratch (device globals; no allocs allowed) ----------------
__device__ float g_x   [NC];
__device__ float g_xag [NC];
__device__ float g_P   [NC];
__device__ float g_Q   [NC];
__device__ float g_a   [NC];
__device__ float g_xv2 [NC];
__device__ float g_bP  [3*NC];
__device__ float g_bQ  [3*NC];
__device__ float g_bh  [3*NC];
__device__ float g_bs  [3*NC];
__device__ float g_ares[NNODE];
__device__ int   g_bcnt[3*NNODE];
__device__ float g_WP  [4*CC*CC];
__device__ int2  g_elist[6][EMAX];   // 0:vpa(-3) 1:audio(-2) 2:acv(3) 3:[0,1] 4:[-1,0] 5:[-1,1]
__device__ int   g_ecnt[6];

// ---------------- small helpers ----------------
__device__ __forceinline__ uint32_t f2tf(float x) {
    uint32_t r;
    asm("cvt.rna.tf32.f32 %0, %1;\n" : "=r"(r) : "f"(x));
    return r;
}
__device__ __forceinline__ void cpasync16(void* dst, const void* src) {
    uint32_t d = (uint32_t)__cvta_generic_to_shared(dst);
    asm volatile("cp.async.cg.shared.global [%0], [%1], 16;\n" :: "r"(d), "l"(src));
}
#define CP_COMMIT()  asm volatile("cp.async.commit_group;\n")
#define CP_WAIT(n)   asm volatile("cp.async.wait_group %0;\n" :: "n"(n))

__device__ __forceinline__ void mma_tf32(float* c, const uint32_t* a, const uint32_t* b) {
    asm volatile(
        "mma.sync.aligned.m16n8k8.row.col.f32.tf32.tf32.f32 "
        "{%0,%1,%2,%3}, {%4,%5,%6,%7}, {%8,%9}, {%0,%1,%2,%3};\n"
        : "+f"(c[0]), "+f"(c[1]), "+f"(c[2]), "+f"(c[3])
        : "r"(a[0]), "r"(a[1]), "r"(a[2]), "r"(a[3]), "r"(b[0]), "r"(b[1]));
}

// ---------------- utility kernels ----------------
// one pass zeroing all atomic-accumulated buffers (10 x NC floats)
__global__ void zero_all() {
    int i = blockIdx.x * 256 + threadIdx.x;       // NC/4 threads total
    float4 z = make_float4(0.f, 0.f, 0.f, 0.f);
    ((float4*)g_x  )[i] = z;
    ((float4*)g_xag)[i] = z;
    ((float4*)g_a  )[i] = z;
    ((float4*)g_xv2)[i] = z;
    #pragma unroll
    for (int b = 0; b < 3; b++) {
        ((float4*)g_bh)[b*(NC/4) + i] = z;
        ((float4*)g_bs)[b*(NC/4) + i] = z;
    }
}
__global__ void prep_wp(const float* __restrict__ w0, const float* __restrict__ w1,
                        const float* __restrict__ w2, const float* __restrict__ w3) {
    int i = blockIdx.x * blockDim.x + threadIdx.x;
    if (i >= 4*CC*CC) return;
    int conv = i >> 14, j = i & 16383;
    const float* W = conv == 0 ? w0 : conv == 1 ? w1 : conv == 2 ? w2 : w3;
    g_WP[i] = W[j] - W[CC*CC + j];
}

// ---------------- edge compaction (warp-aggregated) ----------------
__global__ void compact_edges(const int* __restrict__ src, const int* __restrict__ dst,
                              const int* __restrict__ attr, int E) {
    int e = blockIdx.x * blockDim.x + threadIdx.x;
    if (e >= E) return;
    int a = attr[e];
    int2 sd = make_int2(src[e], dst[e]);
    bool pr[6];
    pr[0] = (a == -3);
    pr[1] = (a == -2);
    pr[2] = (a ==  3);
    pr[3] = (a >=  0) && (a <= 1);
    pr[4] = (a >= -1) && (a <= 0);
    pr[5] = (a >= -1) && (a <= 1);
    int lane = threadIdx.x & 31;
    #pragma unroll
    for (int i = 0; i < 6; i++) {
        unsigned mask = __ballot_sync(0xffffffffu, pr[i]);
        if (pr[i]) {
            int leader = __ffs(mask) - 1;
            int pos = 0;
            if (lane == leader) pos = atomicAdd(&g_ecnt[i], __popc(mask));
            pos = __shfl_sync(mask, pos, leader);
            int rank = __popc(mask & ((1u << lane) - 1));
            g_elist[i][pos + rank] = sd;
        }
    }
}

// ============= fused split-K projection (visual + audio in one launch) ==============
// BM=64 BN=128 BK=16, blockIdx.y = K-split (4 x 256), atomicAdd epilogue.
__global__ void __launch_bounds__(256) gemm_proj(
    const float* __restrict__ xv, const float* __restrict__ Wv, const float* __restrict__ bv,
    const float* __restrict__ xa, const float* __restrict__ Wa, const float* __restrict__ ba)
{
    __shared__ float As[2][64][20];
    __shared__ float Bs[2][16][136];
    const int bx = blockIdx.x;
    const float* A; const float* W; const float* bias; float* Cout; int block_row;
    if (bx < MV/64) { A = xv; W = Wv; bias = bv; Cout = g_x;                   block_row = bx * 64; }
    else            { A = xa; W = Wa; bias = ba; Cout = g_x + (size_t)MV*CC;   block_row = (bx - MV/64) * 64; }

    const int tid  = threadIdx.x;
    const int warp = tid >> 5, lane = tid & 31;
    const int wm = warp >> 2;
    const int wn = warp & 3;
    const int ks = blockIdx.y;
    const int kbase = ks * 256;
    const int lq = lane >> 2, lr = lane & 3;

    float acc[2][4][4];
    #pragma unroll
    for (int mt = 0; mt < 2; mt++)
        #pragma unroll
        for (int nt = 0; nt < 4; nt++)
            #pragma unroll
            for (int i = 0; i < 4; i++) acc[mt][nt][i] = 0.f;

    const int nk = 16;
    {
        {
            int r = tid >> 2, c4 = (tid & 3) * 4;
            cpasync16(&As[0][r][c4], &A[(size_t)(block_row + r) * FDIM + kbase + c4]);
        }
        #pragma unroll
        for (int l = 0; l < 2; l++) {
            int idx = tid * 2 + l;
            int r = idx >> 5, c4 = (idx & 31) * 4;
            cpasync16(&Bs[0][r][c4], &W[(size_t)(kbase + r) * CC + c4]);
        }
        CP_COMMIT();
    }

    for (int kk = 0; kk < nk; kk++) {
        int st = kk & 1;
        if (kk + 1 < nk) {
            int ns = st ^ 1, k0 = kbase + (kk + 1) * 16;
            {
                int r = tid >> 2, c4 = (tid & 3) * 4;
                cpasync16(&As[ns][r][c4], &A[(size_t)(block_row + r) * FDIM + k0 + c4]);
            }
            #pragma unroll
            for (int l = 0; l < 2; l++) {
                int idx = tid * 2 + l;
                int r = idx >> 5, c4 = (idx & 31) * 4;
                cpasync16(&Bs[ns][r][c4], &W[(size_t)(k0 + r) * CC + c4]);
            }
            CP_COMMIT();
            CP_WAIT(1);
        } else {
            CP_WAIT(0);
        }
        __syncthreads();

        #pragma unroll
        for (int kss = 0; kss < 2; kss++) {
            const int k0 = kss * 8;
            uint32_t af[2][4], bf[4][2];
            const int arow0 = wm * 32 + lq;
            #pragma unroll
            for (int mt = 0; mt < 2; mt++) {
                int r = arow0 + mt * 16;
                af[mt][0] = f2tf(As[st][r    ][k0 + lr    ]);
                af[mt][1] = f2tf(As[st][r + 8][k0 + lr    ]);
                af[mt][2] = f2tf(As[st][r    ][k0 + lr + 4]);
                af[mt][3] = f2tf(As[st][r + 8][k0 + lr + 4]);
            }
            #pragma unroll
            for (int nt = 0; nt < 4; nt++) {
                int col = wn * 32 + nt * 8 + lq;
                bf[nt][0] = f2tf(Bs[st][k0 + lr    ][col]);
                bf[nt][1] = f2tf(Bs[st][k0 + lr + 4][col]);
            }
            #pragma unroll
            for (int mt = 0; mt < 2; mt++)
                #pragma unroll
                for (int nt = 0; nt < 4; nt++)
                    mma_tf32(acc[mt][nt], af[mt], bf[nt]);
        }
        __syncthreads();
    }

    #pragma unroll
    for (int mt = 0; mt < 2; mt++) {
        #pragma unroll
        for (int half = 0; half < 2; half++) {
            int row = block_row + wm * 32 + mt * 16 + lq + half * 8;
            #pragma unroll
            for (int nt = 0; nt < 4; nt++) {
                int col = wn * 32 + nt * 8 + lr * 2;
                float v0 = acc[mt][nt][half * 2 + 0];
                float v1 = acc[mt][nt][half * 2 + 1];
                if (ks == 0) { v0 += bias[col]; v1 += bias[col + 1]; }
                atomicAdd(&Cout[(size_t)row * CC + col    ], v0);
                atomicAdd(&Cout[(size_t)row * CC + col + 1], v1);
            }
        }
    }
}

// ===== dual-weight GEMM body: P = relu(A)@W1+b1 ; Q = relu(A)@W2  (BM=64, BN=256) ===
__device__ __forceinline__ void dual_body(
    const float* __restrict__ A,
    const float* __restrict__ W1, const float* __restrict__ b1,
    const float* __restrict__ W2,
    float* __restrict__ C1, float* __restrict__ C2, int block_row)
{
    __shared__ float As[2][64][20];
    __shared__ float Bs[2][16][264];
    const int tid  = threadIdx.x;
    const int warp = tid >> 5, lane = tid & 31;
    const int wm = warp >> 2;
    const int wn = warp & 3;
    const int lq = lane >> 2, lr = lane & 3;

    float acc[2][8][4];
    #pragma unroll
    for (int mt = 0; mt < 2; mt++)
        #pragma unroll
        for (int nt = 0; nt < 8; nt++)
            #pragma unroll
            for (int i = 0; i < 4; i++) acc[mt][nt][i] = 0.f;

    const int nk = 8;
    {
        {
            int r = tid >> 2, c4 = (tid & 3) * 4;
            cpasync16(&As[0][r][c4], &A[(size_t)(block_row + r) * CC + c4]);
        }
        #pragma unroll
        for (int l = 0; l < 4; l++) {
            int idx = tid * 4 + l;
            int r = idx >> 6, c = (idx & 63) * 4;
            const float* s = (c < 128) ? &W1[(size_t)r * CC + c] : &W2[(size_t)r * CC + (c - 128)];
            cpasync16(&Bs[0][r][c], s);
        }
        CP_COMMIT();
    }

    for (int kk = 0; kk < nk; kk++) {
        int st = kk & 1;
        if (kk + 1 < nk) {
            int ns = st ^ 1, k0 = (kk + 1) * 16;
            {
                int r = tid >> 2, c4 = (tid & 3) * 4;
                cpasync16(&As[ns][r][c4], &A[(size_t)(block_row + r) * CC + k0 + c4]);
            }
            #pragma unroll
            for (int l = 0; l < 4; l++) {
                int idx = tid * 4 + l;
                int r = idx >> 6, c = (idx & 63) * 4;
                const float* s = (c < 128) ? &W1[(size_t)(k0 + r) * CC + c]
                                           : &W2[(size_t)(k0 + r) * CC + (c - 128)];
                cpasync16(&Bs[ns][r][c], s);
            }
            CP_COMMIT();
            CP_WAIT(1);
        } else {
            CP_WAIT(0);
        }
        __syncthreads();

        #pragma unroll
        for (int kss = 0; kss < 2; kss++) {
            const int k0 = kss * 8;
            uint32_t af[2][4], bf[8][2];
            const int arow0 = wm * 32 + lq;
            #pragma unroll
            for (int mt = 0; mt < 2; mt++) {
                int r = arow0 + mt * 16;
                af[mt][0] = f2tf(fmaxf(As[st][r    ][k0 + lr    ], 0.f));
                af[mt][1] = f2tf(fmaxf(As[st][r + 8][k0 + lr    ], 0.f));
                af[mt][2] = f2tf(fmaxf(As[st][r    ][k0 + lr + 4], 0.f));
                af[mt][3] = f2tf(fmaxf(As[st][r + 8][k0 + lr + 4], 0.f));
            }
            #pragma unroll
            for (int nt = 0; nt < 8; nt++) {
                int col = wn * 64 + nt * 8 + lq;
                bf[nt][0] = f2tf(Bs[st][k0 + lr    ][col]);
                bf[nt][1] = f2tf(Bs[st][k0 + lr + 4][col]);
            }
            #pragma unroll
            for (int mt = 0; mt < 2; mt++)
                #pragma unroll
                for (int nt = 0; nt < 8; nt++)
                    mma_tf32(acc[mt][nt], af[mt], bf[nt]);
        }
        __syncthreads();
    }

    const bool first = (wn < 2);
    float* Cout = first ? C1 : C2;
    const int colbase = (first ? wn : (wn - 2)) * 64;
    #pragma unroll
    for (int mt = 0; mt < 2; mt++) {
        #pragma unroll
        for (int half = 0; half < 2; half++) {
            int row = block_row + wm * 32 + mt * 16 + lq + half * 8;
            #pragma unroll
            for (int nt = 0; nt < 8; nt++) {
                int col = colbase + nt * 8 + lr * 2;
                float v0 = acc[mt][nt][half * 2 + 0];
                float v1 = acc[mt][nt][half * 2 + 1];
                if (first) { v0 += b1[col]; v1 += b1[col + 1]; }
                *(float2*)&Cout[(size_t)row * CC + col] = make_float2(v0, v1);
            }
        }
    }
}

__global__ void __launch_bounds__(256) gemm_dualA(
    const float* __restrict__ A, const float* __restrict__ W1, const float* __restrict__ b1,
    const float* __restrict__ W2, float* __restrict__ C1, float* __restrict__ C2)
{
    dual_body(A, W1, b1, W2, C1, C2, blockIdx.x * 64);
}

struct Dual3Args { const float* W1[3]; const float* b1[3]; const float* W2[3]; };
__global__ void __launch_bounds__(256) gemm_dual3(const float* __restrict__ A, Dual3Args da) {
    const int by = blockIdx.y;
    dual_body(A, da.W1[by], da.b1[by], da.W2[by],
              g_bP + (size_t)by * NC, g_bQ + (size_t)by * NC, blockIdx.x * 64);
}

// ---------------- tensor-core EdgeConv body (batched, compacted list) ----------------
#define W2S_STRIDE 136
#define ZS_STRIDE  132
#define SMEM_W2S_WORDS (128*W2S_STRIDE)
#define SMEM_ZS_WORDS  (32*ZS_STRIDE)
#define SMEM_CONV_BYTES ((SMEM_W2S_WORDS + SMEM_ZS_WORDS + 128 + 64 + 16) * 4)

__device__ __forceinline__ void conv_body(
    const int2* __restrict__ list, const int* __restrict__ cntp,
    const float* __restrict__ W2, const float* __restrict__ b2,
    const float* __restrict__ P, const float* __restrict__ Q,
    float* __restrict__ out)
{
    extern __shared__ uint32_t dsm[];
    uint32_t* W2s  = dsm;
    uint32_t* Zs   = dsm + SMEM_W2S_WORDS;
    float*    b2s  = (float*)(dsm + SMEM_W2S_WORDS + SMEM_ZS_WORDS);
    int2*     spair= (int2*)(b2s + 128);

    const int tid  = threadIdx.x;
    const int warp = tid >> 5, lane = tid & 31;
    const int lq = lane >> 2, lr = lane & 3;
    const int wr = warp >> 2;
    const int wc = warp & 3;

    for (int i = tid; i < CC*CC; i += 256)
        W2s[(i >> 7) * W2S_STRIDE + (i & 127)] = f2tf(W2[i]);
    if (tid < 128) b2s[tid] = b2[tid];

    const int n = *cntp;
    const float4* P4 = (const float4*)P;
    const float4* Q4 = (const float4*)Q;

    for (int batch = blockIdx.x; batch * 32 < n; batch += gridDim.x) {
        const int base = batch * 32;
        const int m = min(32, n - base);
        __syncthreads();
        if (tid < 32)
            spair[tid] = (tid < m) ? list[base + tid] : make_int2(0, 0);
        __syncthreads();

        {
            int e = tid >> 3, part = tid & 7;
            int2 sd = spair[e];
            uint32_t* zrow = &Zs[e * ZS_STRIDE + part * 16];
            if (e < m) {
                const float4* pr = &P4[(size_t)sd.y * 32 + part * 4];
                const float4* qr = &Q4[(size_t)sd.x * 32 + part * 4];
                #pragma unroll
                for (int j = 0; j < 4; j++) {
                    float4 p = __ldg(&pr[j]);
                    float4 q = __ldg(&qr[j]);
                    uint4 z;
                    z.x = f2tf(fmaxf(p.x + q.x, 0.f));
                    z.y = f2tf(fmaxf(p.y + q.y, 0.f));
                    z.z = f2tf(fmaxf(p.z + q.z, 0.f));
                    z.w = f2tf(fmaxf(p.w + q.w, 0.f));
                    *(uint4*)&zrow[j * 4] = z;
                }
            } else {
                #pragma unroll
                for (int j = 0; j < 4; j++)
                    *(uint4*)&zrow[j * 4] = make_uint4(0, 0, 0, 0);
            }
        }
        __syncthreads();

        float acc[4][4];
        #pragma unroll
        for (int nt = 0; nt < 4; nt++)
            #pragma unroll
            for (int i = 0; i < 4; i++) acc[nt][i] = 0.f;

        const int r0 = wr * 16 + lq;
        #pragma unroll
        for (int ks = 0; ks < 16; ks++) {
            uint32_t af[4];
            af[0] = Zs[ r0      * ZS_STRIDE + ks * 8 + lr    ];
            af[1] = Zs[(r0 + 8) * ZS_STRIDE + ks * 8 + lr    ];
            af[2] = Zs[ r0      * ZS_STRIDE + ks * 8 + lr + 4];
            af[3] = Zs[(r0 + 8) * ZS_STRIDE + ks * 8 + lr + 4];
            #pragma unroll
            for (int nt = 0; nt < 4; nt++) {
                uint32_t bf[2];
                int col = wc * 32 + nt * 8 + lq;
                bf[0] = W2s[(ks * 8 + lr    ) * W2S_STRIDE + col];
                bf[1] = W2s[(ks * 8 + lr + 4) * W2S_STRIDE + col];
                mma_tf32(acc[nt], af, bf);
            }
        }

        #pragma unroll
        for (int half = 0; half < 2; half++) {
            int rr = wr * 16 + lq + half * 8;
            if (rr < m) {
                int d = spair[rr].y;
                float* orow = &out[(size_t)d * CC];
                #pragma unroll
                for (int nt = 0; nt < 4; nt++) {
                    int col = wc * 32 + nt * 8 + lr * 2;
                    float v0 = fmaxf(acc[nt][half * 2 + 0] + b2s[col    ], 0.f);
                    float v1 = fmaxf(acc[nt][half * 2 + 1] + b2s[col + 1], 0.f);
                    atomicMax((int*)&orow[col    ], __float_as_int(v0));
                    atomicMax((int*)&orow[col + 1], __float_as_int(v1));
                }
            }
        }
    }
}

__global__ void __launch_bounds__(256) conv_tcA(
    const int2* __restrict__ list, const int* __restrict__ cntp,
    const float* __restrict__ W2, const float* __restrict__ b2,
    const float* __restrict__ P, const float* __restrict__ Q,
    float* __restrict__ out)
{
    conv_body(list, cntp, W2, b2, P, Q, out);
}

struct Conv3Args { const float* W2[3]; const float* b2[3]; };
__global__ void __launch_bounds__(256) conv_tc3(Conv3Args ca) {
    const int by = blockIdx.y;
    conv_body(g_elist[3 + by], &g_ecnt[3 + by], ca.W2[by], ca.b2[by],
              g_bP + (size_t)by * NC, g_bQ + (size_t)by * NC, g_bh + (size_t)by * NC);
}

// ---------------- vectorized scatter kernels over compacted lists ----------------
__global__ void __launch_bounds__(256) edge_vpa2() {
    const int n = g_ecnt[0];
    const int part = threadIdx.x & 31;
    const float4* X4 = (const float4*)g_x;
    for (int i = blockIdx.x * 8 + (threadIdx.x >> 5); i < n; i += gridDim.x * 8) {
        int2 sd = g_elist[0][i];
        float4 xs = __ldg(&X4[(size_t)sd.x * 32 + part]);
        float4 xd = __ldg(&X4[(size_t)sd.y * 32 + part]);
        float* orow = &g_xag[(size_t)sd.y * CC + part * 4];
        atomicMax((int*)&orow[0], __float_as_int(fmaxf(xs.x + xd.x, 0.f)));
        atomicMax((int*)&orow[1], __float_as_int(fmaxf(xs.y + xd.y, 0.f)));
        atomicMax((int*)&orow[2], __float_as_int(fmaxf(xs.z + xd.z, 0.f)));
        atomicMax((int*)&orow[3], __float_as_int(fmaxf(xs.w + xd.w, 0.f)));
    }
}
__global__ void __launch_bounds__(256) edge_acv2() {
    const int n = g_ecnt[2];
    const int part = threadIdx.x & 31;
    const float4* X4 = (const float4*)g_x;
    for (int i = blockIdx.x * 8 + (threadIdx.x >> 5); i < n; i += gridDim.x * 8) {
        int2 sd = g_elist[2][i];
        float w = g_ares[sd.x];
        float4 xs = __ldg(&X4[(size_t)sd.x * 32 + part]);
        float4 xd = __ldg(&X4[(size_t)sd.y * 32 + part]);
        float* orow = &g_xv2[(size_t)sd.y * CC + part * 4];
        atomicAdd(&orow[0], w * xs.x + xd.x);
        atomicAdd(&orow[1], w * xs.y + xd.y);
        atomicAdd(&orow[2], w * xs.z + xd.z);
        atomicAdd(&orow[3], w * xs.w + xd.w);
    }
}
// all 3 branches in one launch (blockIdx.y = branch)
__global__ void __launch_bounds__(256) edge_sage3() {
    const int by = blockIdx.y;
    const int n = g_ecnt[3 + by];
    const int2* list = g_elist[3 + by];
    float* sbuf = g_bs + (size_t)by * NC;
    int*   cnt  = g_bcnt + by * NNODE;
    const float4* H4 = (const float4*)(g_bh + (size_t)by * NC);
    const int part = threadIdx.x & 31;
    for (int i = blockIdx.x * 8 + (threadIdx.x >> 5); i < n; i += gridDim.x * 8) {
        int2 sd = list[i];
        float4 hs = __ldg(&H4[(size_t)sd.x * 32 + part]);
        float* orow = &sbuf[(size_t)sd.y * CC + part * 4];
        atomicAdd(&orow[0], hs.x);
        atomicAdd(&orow[1], hs.y);
        atomicAdd(&orow[2], hs.z);
        atomicAdd(&orow[3], hs.w);
        if (part == 0) atomicAdd(&cnt[sd.y], 1);
    }
}

// a_res = a @ fc_W + fc_b
__global__ void ares_kernel(const float* __restrict__ fcW, const float* __restrict__ fcb) {
    int warp = (blockIdx.x * blockDim.x + threadIdx.x) >> 5;
    int lane = threadIdx.x & 31;
    if (warp >= NNODE) return;
    const float* ap = &g_a[(size_t)warp * CC];
    float acc = 0.f;
    #pragma unroll
    for (int k = 0; k < 4; k++) acc += ap[lane + 32*k] * fcW[lane + 32*k];
    #pragma unroll
    for (int o = 16; o > 0; o >>= 1) acc += __shfl_xor_sync(0xffffffffu, acc, o);
    if (lane == 0) g_ares[warp] = acc + fcb[0];
}

// ===== final SAGE GEMM, output rows only, 3 branches, mean folded, atomicAdd->d_out ===
// per branch: dout[g*128+r,:] += relu( (s/cnt)[node]@Wl + bl + h[node]@Wr ),
// node = g*node_stride + r.   BM=128, concat-K=256, grid (groups, 3).
__global__ void __launch_bounds__(256) gemm_sage3(
    const float* __restrict__ Wl, const float* __restrict__ bl,
    const float* __restrict__ Wr, float* __restrict__ dout, int node_stride)
{
    __shared__ float As[2][128][20];
    __shared__ float Bs[2][16][136];
    const int by = blockIdx.y;
    const float* A1 = g_bs + (size_t)by * NC;
    const float* A2 = g_bh + (size_t)by * NC;
    const int*  cnt = g_bcnt + by * NNODE;
    const int tid  = threadIdx.x;
    const int warp = tid >> 5, lane = tid & 31;
    const int wm = warp >> 1;
    const int wn = warp & 1;
    const int lq = lane >> 2, lr = lane & 3;
    const int node0 = blockIdx.x * node_stride;
    const int out0  = blockIdx.x * 128;

    // mean reciprocals for the 4 A-rows this thread touches
    float rinv[4];
    #pragma unroll
    for (int j = 0; j < 4; j++) {
        int c = cnt[node0 + wm * 32 + lq + j * 8];
        rinv[j] = 1.f / (float)(c > 1 ? c : 1);
    }

    float acc[2][8][4];
    #pragma unroll
    for (int mt = 0; mt < 2; mt++)
        #pragma unroll
        for (int nt = 0; nt < 8; nt++)
            #pragma unroll
            for (int i = 0; i < 4; i++) acc[mt][nt][i] = 0.f;

    const int nk = 16;     // concat K=256
    {
        #pragma unroll
        for (int l = 0; l < 2; l++) {
            int idx = tid * 2 + l;
            int r = idx >> 2, c4 = (idx & 3) * 4;
            cpasync16(&As[0][r][c4], &A1[(size_t)(node0 + r) * CC + c4]);
        }
        #pragma unroll
        for (int l = 0; l < 2; l++) {
            int idx = tid * 2 + l;
            int r = idx >> 5, c4 = (idx & 31) * 4;
            cpasync16(&Bs[0][r][c4], &Wl[(size_t)r * CC + c4]);
        }
        CP_COMMIT();
    }

    for (int kk = 0; kk < nk; kk++) {
        int st = kk & 1;
        if (kk + 1 < nk) {
            int ns = st ^ 1;
            int kn = kk + 1;
            const float* Asrc = (kn < 8) ? A1 : A2;
            const float* Wsrc = (kn < 8) ? Wl : Wr;
            int k0 = (kn & 7) * 16;
            #pragma unroll
            for (int l = 0; l < 2; l++) {
                int idx = tid * 2 + l;
                int r = idx >> 2, c4 = (idx & 3) * 4;
                cpasync16(&As[ns][r][c4], &Asrc[(size_t)(node0 + r) * CC + k0 + c4]);
            }
            #pragma unroll
            for (int l = 0; l < 2; l++) {
                int idx = tid * 2 + l;
                int r = idx >> 5, c4 = (idx & 31) * 4;
                cpasync16(&Bs[ns][r][c4], &Wsrc[(size_t)(k0 + r) * CC + c4]);
            }
            CP_COMMIT();
            CP_WAIT(1);
        } else {
            CP_WAIT(0);
        }
        __syncthreads();

        const bool isA1 = (kk < 8);
        #pragma unroll
        for (int kss = 0; kss < 2; kss++) {
            const int k0 = kss * 8;
            uint32_t af[2][4], bf[8][2];
            const int arow0 = wm * 32 + lq;
            #pragma unroll
            for (int mt = 0; mt < 2; mt++) {
                int r = arow0 + mt * 16;
                float s0 = isA1 ? rinv[mt*2    ] : 1.f;
                float s1 = isA1 ? rinv[mt*2 + 1] : 1.f;
                af[mt][0] = f2tf(As[st][r    ][k0 + lr    ] * s0);
                af[mt][1] = f2tf(As[st][r + 8][k0 + lr    ] * s1);
                af[mt][2] = f2tf(As[st][r    ][k0 + lr + 4] * s0);
                af[mt][3] = f2tf(As[st][r + 8][k0 + lr + 4] * s1);
            }
            #pragma unroll
            for (int nt = 0; nt < 8; nt++) {
                int col = wn * 64 + nt * 8 + lq;
                bf[nt][0] = f2tf(Bs[st][k0 + lr    ][col]);
                bf[nt][1] = f2tf(Bs[st][k0 + lr + 4][col]);
            }
            #pragma unroll
            for (int mt = 0; mt < 2; mt++)
                #pragma unroll
                for (int nt = 0; nt < 8; nt++)
                    mma_tf32(acc[mt][nt], af[mt], bf[nt]);
        }
        __syncthreads();
    }

    #pragma unroll
    for (int mt = 0; mt < 2; mt++) {
        #pragma unroll
        for (int half = 0; half < 2; half++) {
            int orow = out0 + wm * 32 + mt * 16 + lq + half * 8;
            #pragma unroll
            for (int nt = 0; nt < 8; nt++) {
                int col = wn * 64 + nt * 8 + lr * 2;
                float v0 = fmaxf(acc[mt][nt][half * 2 + 0] + bl[col    ], 0.f);
                float v1 = fmaxf(acc[mt][nt][half * 2 + 1] + bl[col + 1], 0.f);
                atomicAdd(&dout[(size_t)orow * CC + col    ], v0);
                atomicAdd(&dout[(size_t)orow * CC + col + 1], v1);
            }
        }
    }
}

// ---------------- host orchestration ----------------
static inline void* symv(const void* s) {
    void* p = nullptr;
    cudaGetSymbolAddress(&p, (const void*)s);
    return p;
}

extern "C" void kernel_launch(void* const* d_in, const int* in_sizes, int n_in,
                              void* d_out, int out_size) {
    const float* x_visual = (const float*)d_in[0];
    const float* x_audio  = (const float*)d_in[1];
    const float* W011 = (const float*)d_in[2];  const float* b011 = (const float*)d_in[3];
    const float* W012 = (const float*)d_in[4];  const float* b012 = (const float*)d_in[5];
    const float* ecW1[4] = {(const float*)d_in[6],  (const float*)d_in[10],
                            (const float*)d_in[14], (const float*)d_in[18]};
    const float* ecb1[4] = {(const float*)d_in[7],  (const float*)d_in[11],
                            (const float*)d_in[15], (const float*)d_in[19]};
    const float* ecW2[4] = {(const float*)d_in[8],  (const float*)d_in[12],
                            (const float*)d_in[16], (const float*)d_in[20]};
    const float* ecb2[4] = {(const float*)d_in[9],  (const float*)d_in[13],
                            (const float*)d_in[17], (const float*)d_in[21]};
    const float* Wl  = (const float*)d_in[22];
    const float* bl  = (const float*)d_in[23];
    const float* Wr  = (const float*)d_in[24];
    const float* fcW = (const float*)d_in[25];
    const float* fcb = (const float*)d_in[26];
    const int*   eidx = (const int*)d_in[27];
    const int*   attr = (const int*)d_in[28];
    const int E = in_sizes[27] / 2;
    const int* srcp = eidx;
    const int* dstp = eidx + E;

    float* pxag = (float*)symv(g_xag);
    float* pP   = (float*)symv(g_P);    float* pQ   = (float*)symv(g_Q);
    float* pa   = (float*)symv(g_a);    float* pxv2 = (float*)symv(g_xv2);
    float* pwp  = (float*)symv(g_WP);
    int*   pecnt= (int*)symv(g_ecnt);
    int*   pbcnt= (int*)symv(g_bcnt);
    int2*  plist= (int2*)symv(g_elist);

    const int SCAT_GRID = 1184;

    cudaFuncSetAttribute(conv_tcA, cudaFuncAttributeMaxDynamicSharedMemorySize, SMEM_CONV_BYTES);
    cudaFuncSetAttribute(conv_tc3, cudaFuncAttributeMaxDynamicSharedMemorySize, SMEM_CONV_BYTES);

    // zeroing + small memsets
    cudaMemsetAsync(pecnt, 0, 6 * sizeof(int));
    cudaMemsetAsync(pbcnt, 0, 3 * NNODE * sizeof(int));
    cudaMemsetAsync(d_out, 0, (size_t)out_size * sizeof(float));
    zero_all<<<NC/4/256, 256>>>();

    compact_edges<<<(E + 255)/256, 256>>>(srcp, dstp, attr, E);
    prep_wp<<<(4*CC*CC + 255)/256, 256>>>(ecW1[0], ecW1[1], ecW1[2], ecW1[3]);

    // fused input projections -> g_x
    gemm_proj<<<dim3(NNODE/64, 4), 256>>>(x_visual, W011, b011, x_audio, W012, b012);

    // xa_g = relu(seg_max over vpa edges of x[dst]+x[src])
    edge_vpa2<<<SCAT_GRID, 256>>>();

    // convA: a = relu(EdgeConv(xa_g; attr==-2))
    gemm_dualA<<<NNODE/64, 256>>>(pxag, pwp, ecb1[0], ecW1[0]+CC*CC, pP, pQ);
    conv_tcA<<<296, 256, SMEM_CONV_BYTES>>>(plist + 1*EMAX, pecnt + 1,
                                            ecW2[0], ecb2[0], pP, pQ, pa);

    ares_kernel<<<NNODE/8, 256>>>(fcW, fcb);

    // xv2 raw sums (relu folded into gemm_dual3's A conversion)
    edge_acv2<<<SCAT_GRID, 256>>>();

    // 3 branches batched per stage
    Dual3Args da;
    Conv3Args ca;
    for (int b = 0; b < 3; b++) {
        da.W1[b] = pwp + (b + 1) * CC * CC;
        da.b1[b] = ecb1[b + 1];
        da.W2[b] = ecW1[b + 1] + CC * CC;
        ca.W2[b] = ecW2[b + 1];
        ca.b2[b] = ecb2[b + 1];
    }
    gemm_dual3<<<dim3(NNODE/64, 3), 256>>>(pxv2, da);
    conv_tc3<<<dim3(148, 3), 256, SMEM_CONV_BYTES>>>(ca);
    edge_sage3<<<dim3(592, 3), 256>>>();

    // final: dout[g*128+r] = sum_b relu(mean_b@Wl + bl + h_b@Wr) on output rows only
    int groups = out_size / (TT * CC);      // 64
    int step   = MV / groups;               // speakers*T = 384
    gemm_sage3<<<dim3(groups, 3), 256>>>(Wl, bl, Wr, (float*)d_out, step);
}

// round 10
// speedup vs baseline: 4.4691x; 1.1019x over previous
#include <cuda_runtime.h>
#include <cstdint>

// ---------------- fixed problem dims ----------------
#define NVIS   192
#define NAUD   64
#define TT     128
#define FDIM   1024
#define CC     128
#define MV     (NVIS*TT)      // 24576 visual nodes
#define MA     (NAUD*TT)      // 8192  audio nodes
#define NNODE  (MV+MA)        // 32768
#define NC     (NNODE*CC)     // 4194304
#define EMAX   262144

// ---------------- scratch (device globals; no allocs allowed) ----------------
__device__ float g_x   [NC];
__device__ float g_xag [NC];
__device__ float g_P   [NC];
__device__ float g_Q   [NC];
__device__ float g_a   [NC];
__device__ float g_xv2 [NC];
__device__ float g_bP  [3*NC];
__device__ float g_bQ  [3*NC];
__device__ float g_bh  [3*NC];
__device__ float g_bs  [3*NC];
__device__ float g_ares[NNODE];
__device__ int   g_bcnt[3*NNODE];
__device__ float g_WP  [4*CC*CC];
__device__ int2  g_elist[6][EMAX];   // 0:vpa(-3) 1:audio(-2) 2:acv(3) 3:[0,1] 4:[-1,0] 5:[-1,1]
__device__ int   g_ecnt[6];

// ---------------- small helpers ----------------
__device__ __forceinline__ uint32_t f2tf(float x) {
    uint32_t r;
    asm("cvt.rna.tf32.f32 %0, %1;\n" : "=r"(r) : "f"(x));
    return r;
}
__device__ __forceinline__ void cpasync16(void* dst, const void* src) {
    uint32_t d = (uint32_t)__cvta_generic_to_shared(dst);
    asm volatile("cp.async.cg.shared.global [%0], [%1], 16;\n" :: "r"(d), "l"(src));
}
#define CP_COMMIT()  asm volatile("cp.async.commit_group;\n")
#define CP_WAIT(n)   asm volatile("cp.async.wait_group %0;\n" :: "n"(n))

__device__ __forceinline__ void mma_tf32(float* c, const uint32_t* a, const uint32_t* b) {
    asm volatile(
        "mma.sync.aligned.m16n8k8.row.col.f32.tf32.tf32.f32 "
        "{%0,%1,%2,%3}, {%4,%5,%6,%7}, {%8,%9}, {%0,%1,%2,%3};\n"
        : "+f"(c[0]), "+f"(c[1]), "+f"(c[2]), "+f"(c[3])
        : "r"(a[0]), "r"(a[1]), "r"(a[2]), "r"(a[3]), "r"(b[0]), "r"(b[1]));
}
// vectorized global reductions (sm_90+)
__device__ __forceinline__ void red_add_v4(float* addr, float4 v) {
    asm volatile("red.global.add.v4.f32 [%0], {%1, %2, %3, %4};\n"
                 :: "l"(addr), "f"(v.x), "f"(v.y), "f"(v.z), "f"(v.w) : "memory");
}
__device__ __forceinline__ void red_add_v2(float* addr, float a, float b) {
    asm volatile("red.global.add.v2.f32 [%0], {%1, %2};\n"
                 :: "l"(addr), "f"(a), "f"(b) : "memory");
}

// ---------------- utility kernels ----------------
// zero all atomic-accumulated buffers (xag, a, xv2, bh x3, bs x3)
__global__ void zero_all() {
    int i = blockIdx.x * 256 + threadIdx.x;       // NC/4 threads total
    float4 z = make_float4(0.f, 0.f, 0.f, 0.f);
    ((float4*)g_xag)[i] = z;
    ((float4*)g_a  )[i] = z;
    ((float4*)g_xv2)[i] = z;
    #pragma unroll
    for (int b = 0; b < 3; b++) {
        ((float4*)g_bh)[b*(NC/4) + i] = z;
        ((float4*)g_bs)[b*(NC/4) + i] = z;
    }
}
__global__ void prep_wp(const float* __restrict__ w0, const float* __restrict__ w1,
                        const float* __restrict__ w2, const float* __restrict__ w3) {
    int i = blockIdx.x * blockDim.x + threadIdx.x;
    if (i >= 4*CC*CC) return;
    int conv = i >> 14, j = i & 16383;
    const float* W = conv == 0 ? w0 : conv == 1 ? w1 : conv == 2 ? w2 : w3;
    g_WP[i] = W[j] - W[CC*CC + j];
}

// ---------------- edge compaction (warp-aggregated) ----------------
__global__ void compact_edges(const int* __restrict__ src, const int* __restrict__ dst,
                              const int* __restrict__ attr, int E) {
    int e = blockIdx.x * blockDim.x + threadIdx.x;
    if (e >= E) return;
    int a = attr[e];
    int2 sd = make_int2(src[e], dst[e]);
    bool pr[6];
    pr[0] = (a == -3);
    pr[1] = (a == -2);
    pr[2] = (a ==  3);
    pr[3] = (a >=  0) && (a <= 1);
    pr[4] = (a >= -1) && (a <= 0);
    pr[5] = (a >= -1) && (a <= 1);
    int lane = threadIdx.x & 31;
    #pragma unroll
    for (int i = 0; i < 6; i++) {
        unsigned mask = __ballot_sync(0xffffffffu, pr[i]);
        if (pr[i]) {
            int leader = __ffs(mask) - 1;
            int pos = 0;
            if (lane == leader) pos = atomicAdd(&g_ecnt[i], __popc(mask));
            pos = __shfl_sync(mask, pos, leader);
            int rank = __popc(mask & ((1u << lane) - 1));
            g_elist[i][pos + rank] = sd;
        }
    }
}

// ============= fused input projections (visual + audio), full-K, plain store ========
// BM=64 BN=128 BK=16, grid NNODE/64.
__global__ void __launch_bounds__(256) gemm_proj(
    const float* __restrict__ xv, const float* __restrict__ Wv, const float* __restrict__ bv,
    const float* __restrict__ xa, const float* __restrict__ Wa, const float* __restrict__ ba)
{
    __shared__ float As[2][64][20];
    __shared__ float Bs[2][16][136];
    const int bx = blockIdx.x;
    const float* A; const float* W; const float* bias; float* Cout; int block_row;
    if (bx < MV/64) { A = xv; W = Wv; bias = bv; Cout = g_x;                   block_row = bx * 64; }
    else            { A = xa; W = Wa; bias = ba; Cout = g_x + (size_t)MV*CC;   block_row = (bx - MV/64) * 64; }

    const int tid  = threadIdx.x;
    const int warp = tid >> 5, lane = tid & 31;
    const int wm = warp >> 2;
    const int wn = warp & 3;
    const int lq = lane >> 2, lr = lane & 3;

    float acc[2][4][4];
    #pragma unroll
    for (int mt = 0; mt < 2; mt++)
        #pragma unroll
        for (int nt = 0; nt < 4; nt++)
            #pragma unroll
            for (int i = 0; i < 4; i++) acc[mt][nt][i] = 0.f;

    const int nk = FDIM / 16;     // 64
    {
        {
            int r = tid >> 2, c4 = (tid & 3) * 4;
            cpasync16(&As[0][r][c4], &A[(size_t)(block_row + r) * FDIM + c4]);
        }
        #pragma unroll
        for (int l = 0; l < 2; l++) {
            int idx = tid * 2 + l;
            int r = idx >> 5, c4 = (idx & 31) * 4;
            cpasync16(&Bs[0][r][c4], &W[(size_t)r * CC + c4]);
        }
        CP_COMMIT();
    }

    for (int kk = 0; kk < nk; kk++) {
        int st = kk & 1;
        if (kk + 1 < nk) {
            int ns = st ^ 1, k0 = (kk + 1) * 16;
            {
                int r = tid >> 2, c4 = (tid & 3) * 4;
                cpasync16(&As[ns][r][c4], &A[(size_t)(block_row + r) * FDIM + k0 + c4]);
            }
            #pragma unroll
            for (int l = 0; l < 2; l++) {
                int idx = tid * 2 + l;
                int r = idx >> 5, c4 = (idx & 31) * 4;
                cpasync16(&Bs[ns][r][c4], &W[(size_t)(k0 + r) * CC + c4]);
            }
            CP_COMMIT();
            CP_WAIT(1);
        } else {
            CP_WAIT(0);
        }
        __syncthreads();

        #pragma unroll
        for (int kss = 0; kss < 2; kss++) {
            const int k0 = kss * 8;
            uint32_t af[2][4], bf[4][2];
            const int arow0 = wm * 32 + lq;
            #pragma unroll
            for (int mt = 0; mt < 2; mt++) {
                int r = arow0 + mt * 16;
                af[mt][0] = f2tf(As[st][r    ][k0 + lr    ]);
                af[mt][1] = f2tf(As[st][r + 8][k0 + lr    ]);
                af[mt][2] = f2tf(As[st][r    ][k0 + lr + 4]);
                af[mt][3] = f2tf(As[st][r + 8][k0 + lr + 4]);
            }
            #pragma unroll
            for (int nt = 0; nt < 4; nt++) {
                int col = wn * 32 + nt * 8 + lq;
                bf[nt][0] = f2tf(Bs[st][k0 + lr    ][col]);
                bf[nt][1] = f2tf(Bs[st][k0 + lr + 4][col]);
            }
            #pragma unroll
            for (int mt = 0; mt < 2; mt++)
                #pragma unroll
                for (int nt = 0; nt < 4; nt++)
                    mma_tf32(acc[mt][nt], af[mt], bf[nt]);
        }
        __syncthreads();
    }

    #pragma unroll
    for (int mt = 0; mt < 2; mt++) {
        #pragma unroll
        for (int half = 0; half < 2; half++) {
            int row = block_row + wm * 32 + mt * 16 + lq + half * 8;
            #pragma unroll
            for (int nt = 0; nt < 4; nt++) {
                int col = wn * 32 + nt * 8 + lr * 2;
                float v0 = acc[mt][nt][half * 2 + 0] + bias[col];
                float v1 = acc[mt][nt][half * 2 + 1] + bias[col + 1];
                *(float2*)&Cout[(size_t)row * CC + col] = make_float2(v0, v1);
            }
        }
    }
}

// ===== dual-weight GEMM body: P = relu(A)@W1+b1 ; Q = relu(A)@W2  (BM=64, BN=256) ===
__device__ __forceinline__ void dual_body(
    const float* __restrict__ A,
    const float* __restrict__ W1, const float* __restrict__ b1,
    const float* __restrict__ W2,
    float* __restrict__ C1, float* __restrict__ C2, int block_row)
{
    __shared__ float As[2][64][20];
    __shared__ float Bs[2][16][264];
    const int tid  = threadIdx.x;
    const int warp = tid >> 5, lane = tid & 31;
    const int wm = warp >> 2;
    const int wn = warp & 3;
    const int lq = lane >> 2, lr = lane & 3;

    float acc[2][8][4];
    #pragma unroll
    for (int mt = 0; mt < 2; mt++)
        #pragma unroll
        for (int nt = 0; nt < 8; nt++)
            #pragma unroll
            for (int i = 0; i < 4; i++) acc[mt][nt][i] = 0.f;

    const int nk = 8;
    {
        {
            int r = tid >> 2, c4 = (tid & 3) * 4;
            cpasync16(&As[0][r][c4], &A[(size_t)(block_row + r) * CC + c4]);
        }
        #pragma unroll
        for (int l = 0; l < 4; l++) {
            int idx = tid * 4 + l;
            int r = idx >> 6, c = (idx & 63) * 4;
            const float* s = (c < 128) ? &W1[(size_t)r * CC + c] : &W2[(size_t)r * CC + (c - 128)];
            cpasync16(&Bs[0][r][c], s);
        }
        CP_COMMIT();
    }

    for (int kk = 0; kk < nk; kk++) {
        int st = kk & 1;
        if (kk + 1 < nk) {
            int ns = st ^ 1, k0 = (kk + 1) * 16;
            {
                int r = tid >> 2, c4 = (tid & 3) * 4;
                cpasync16(&As[ns][r][c4], &A[(size_t)(block_row + r) * CC + k0 + c4]);
            }
            #pragma unroll
            for (int l = 0; l < 4; l++) {
                int idx = tid * 4 + l;
                int r = idx >> 6, c = (idx & 63) * 4;
                const float* s = (c < 128) ? &W1[(size_t)(k0 + r) * CC + c]
                                           : &W2[(size_t)(k0 + r) * CC + (c - 128)];
                cpasync16(&Bs[ns][r][c], s);
            }
            CP_COMMIT();
            CP_WAIT(1);
        } else {
            CP_WAIT(0);
        }
        __syncthreads();

        #pragma unroll
        for (int kss = 0; kss < 2; kss++) {
            const int k0 = kss * 8;
            uint32_t af[2][4], bf[8][2];
            const int arow0 = wm * 32 + lq;
            #pragma unroll
            for (int mt = 0; mt < 2; mt++) {
                int r = arow0 + mt * 16;
                af[mt][0] = f2tf(fmaxf(As[st][r    ][k0 + lr    ], 0.f));
                af[mt][1] = f2tf(fmaxf(As[st][r + 8][k0 + lr    ], 0.f));
                af[mt][2] = f2tf(fmaxf(As[st][r    ][k0 + lr + 4], 0.f));
                af[mt][3] = f2tf(fmaxf(As[st][r + 8][k0 + lr + 4], 0.f));
            }
            #pragma unroll
            for (int nt = 0; nt < 8; nt++) {
                int col = wn * 64 + nt * 8 + lq;
                bf[nt][0] = f2tf(Bs[st][k0 + lr    ][col]);
                bf[nt][1] = f2tf(Bs[st][k0 + lr + 4][col]);
            }
            #pragma unroll
            for (int mt = 0; mt < 2; mt++)
                #pragma unroll
                for (int nt = 0; nt < 8; nt++)
                    mma_tf32(acc[mt][nt], af[mt], bf[nt]);
        }
        __syncthreads();
    }

    const bool first = (wn < 2);
    float* Cout = first ? C1 : C2;
    const int colbase = (first ? wn : (wn - 2)) * 64;
    #pragma unroll
    for (int mt = 0; mt < 2; mt++) {
        #pragma unroll
        for (int half = 0; half < 2; half++) {
            int row = block_row + wm * 32 + mt * 16 + lq + half * 8;
            #pragma unroll
            for (int nt = 0; nt < 8; nt++) {
                int col = colbase + nt * 8 + lr * 2;
                float v0 = acc[mt][nt][half * 2 + 0];
                float v1 = acc[mt][nt][half * 2 + 1];
                if (first) { v0 += b1[col]; v1 += b1[col + 1]; }
                *(float2*)&Cout[(size_t)row * CC + col] = make_float2(v0, v1);
            }
        }
    }
}

__global__ void __launch_bounds__(256) gemm_dualA(
    const float* __restrict__ A, const float* __restrict__ W1, const float* __restrict__ b1,
    const float* __restrict__ W2, float* __restrict__ C1, float* __restrict__ C2)
{
    dual_body(A, W1, b1, W2, C1, C2, blockIdx.x * 64);
}

struct Dual3Args { const float* W1[3]; const float* b1[3]; const float* W2[3]; };
__global__ void __launch_bounds__(256) gemm_dual3(const float* __restrict__ A, Dual3Args da) {
    const int by = blockIdx.y;
    dual_body(A, da.W1[by], da.b1[by], da.W2[by],
              g_bP + (size_t)by * NC, g_bQ + (size_t)by * NC, blockIdx.x * 64);
}

// ---------------- tensor-core EdgeConv body (batched, compacted list) ----------------
#define W2S_STRIDE 136
#define ZS_STRIDE  132
#define SMEM_W2S_WORDS (128*W2S_STRIDE)
#define SMEM_ZS_WORDS  (32*ZS_STRIDE)
#define SMEM_CONV_BYTES ((SMEM_W2S_WORDS + SMEM_ZS_WORDS + 128 + 64 + 16) * 4)

__device__ __forceinline__ void conv_body(
    const int2* __restrict__ list, const int* __restrict__ cntp,
    const float* __restrict__ W2, const float* __restrict__ b2,
    const float* __restrict__ P, const float* __restrict__ Q,
    float* __restrict__ out)
{
    extern __shared__ uint32_t dsm[];
    uint32_t* W2s  = dsm;
    uint32_t* Zs   = dsm + SMEM_W2S_WORDS;
    float*    b2s  = (float*)(dsm + SMEM_W2S_WORDS + SMEM_ZS_WORDS);
    int2*     spair= (int2*)(b2s + 128);

    const int tid  = threadIdx.x;
    const int warp = tid >> 5, lane = tid & 31;
    const int lq = lane >> 2, lr = lane & 3;
    const int wr = warp >> 2;
    const int wc = warp & 3;

    for (int i = tid; i < CC*CC; i += 256)
        W2s[(i >> 7) * W2S_STRIDE + (i & 127)] = f2tf(W2[i]);
    if (tid < 128) b2s[tid] = b2[tid];

    const int n = *cntp;
    const float4* P4 = (const float4*)P;
    const float4* Q4 = (const float4*)Q;

    for (int batch = blockIdx.x; batch * 32 < n; batch += gridDim.x) {
        const int base = batch * 32;
        const int m = min(32, n - base);
        __syncthreads();
        if (tid < 32)
            spair[tid] = (tid < m) ? list[base + tid] : make_int2(0, 0);
        __syncthreads();

        {
            int e = tid >> 3, part = tid & 7;
            int2 sd = spair[e];
            uint32_t* zrow = &Zs[e * ZS_STRIDE + part * 16];
            if (e < m) {
                const float4* pr = &P4[(size_t)sd.y * 32 + part * 4];
                const float4* qr = &Q4[(size_t)sd.x * 32 + part * 4];
                #pragma unroll
                for (int j = 0; j < 4; j++) {
                    float4 p = __ldg(&pr[j]);
                    float4 q = __ldg(&qr[j]);
                    uint4 z;
                    z.x = f2tf(fmaxf(p.x + q.x, 0.f));
                    z.y = f2tf(fmaxf(p.y + q.y, 0.f));
                    z.z = f2tf(fmaxf(p.z + q.z, 0.f));
                    z.w = f2tf(fmaxf(p.w + q.w, 0.f));
                    *(uint4*)&zrow[j * 4] = z;
                }
            } else {
                #pragma unroll
                for (int j = 0; j < 4; j++)
                    *(uint4*)&zrow[j * 4] = make_uint4(0, 0, 0, 0);
            }
        }
        __syncthreads();

        float acc[4][4];
        #pragma unroll
        for (int nt = 0; nt < 4; nt++)
            #pragma unroll
            for (int i = 0; i < 4; i++) acc[nt][i] = 0.f;

        const int r0 = wr * 16 + lq;
        #pragma unroll
        for (int ks = 0; ks < 16; ks++) {
            uint32_t af[4];
            af[0] = Zs[ r0      * ZS_STRIDE + ks * 8 + lr    ];
            af[1] = Zs[(r0 + 8) * ZS_STRIDE + ks * 8 + lr    ];
            af[2] = Zs[ r0      * ZS_STRIDE + ks * 8 + lr + 4];
            af[3] = Zs[(r0 + 8) * ZS_STRIDE + ks * 8 + lr + 4];
            #pragma unroll
            for (int nt = 0; nt < 4; nt++) {
                uint32_t bf[2];
                int col = wc * 32 + nt * 8 + lq;
                bf[0] = W2s[(ks * 8 + lr    ) * W2S_STRIDE + col];
                bf[1] = W2s[(ks * 8 + lr + 4) * W2S_STRIDE + col];
                mma_tf32(acc[nt], af, bf);
            }
        }

        #pragma unroll
        for (int half = 0; half < 2; half++) {
            int rr = wr * 16 + lq + half * 8;
            if (rr < m) {
                int d = spair[rr].y;
                float* orow = &out[(size_t)d * CC];
                #pragma unroll
                for (int nt = 0; nt < 4; nt++) {
                    int col = wc * 32 + nt * 8 + lr * 2;
                    float v0 = fmaxf(acc[nt][half * 2 + 0] + b2s[col    ], 0.f);
                    float v1 = fmaxf(acc[nt][half * 2 + 1] + b2s[col + 1], 0.f);
                    atomicMax((int*)&orow[col    ], __float_as_int(v0));
                    atomicMax((int*)&orow[col + 1], __float_as_int(v1));
                }
            }
        }
    }
}

__global__ void __launch_bounds__(256) conv_tcA(
    const int2* __restrict__ list, const int* __restrict__ cntp,
    const float* __restrict__ W2, const float* __restrict__ b2,
    const float* __restrict__ P, const float* __restrict__ Q,
    float* __restrict__ out)
{
    conv_body(list, cntp, W2, b2, P, Q, out);
}

struct Conv3Args { const float* W2[3]; const float* b2[3]; };
__global__ void __launch_bounds__(256) conv_tc3(Conv3Args ca) {
    const int by = blockIdx.y;
    conv_body(g_elist[3 + by], &g_ecnt[3 + by], ca.W2[by], ca.b2[by],
              g_bP + (size_t)by * NC, g_bQ + (size_t)by * NC, g_bh + (size_t)by * NC);
}

// ---------------- vectorized scatter kernels over compacted lists ----------------
__global__ void __launch_bounds__(256) edge_vpa2() {
    const int n = g_ecnt[0];
    const int part = threadIdx.x & 31;
    const float4* X4 = (const float4*)g_x;
    for (int i = blockIdx.x * 8 + (threadIdx.x >> 5); i < n; i += gridDim.x * 8) {
        int2 sd = g_elist[0][i];
        float4 xs = __ldg(&X4[(size_t)sd.x * 32 + part]);
        float4 xd = __ldg(&X4[(size_t)sd.y * 32 + part]);
        float* orow = &g_xag[(size_t)sd.y * CC + part * 4];
        atomicMax((int*)&orow[0], __float_as_int(fmaxf(xs.x + xd.x, 0.f)));
        atomicMax((int*)&orow[1], __float_as_int(fmaxf(xs.y + xd.y, 0.f)));
        atomicMax((int*)&orow[2], __float_as_int(fmaxf(xs.z + xd.z, 0.f)));
        atomicMax((int*)&orow[3], __float_as_int(fmaxf(xs.w + xd.w, 0.f)));
    }
}
__global__ void __launch_bounds__(256) edge_acv2() {
    const int n = g_ecnt[2];
    const int part = threadIdx.x & 31;
    const float4* X4 = (const float4*)g_x;
    for (int i = blockIdx.x * 8 + (threadIdx.x >> 5); i < n; i += gridDim.x * 8) {
        int2 sd = g_elist[2][i];
        float w = g_ares[sd.x];
        float4 xs = __ldg(&X4[(size_t)sd.x * 32 + part]);
        float4 xd = __ldg(&X4[(size_t)sd.y * 32 + part]);
        float4 msg = make_float4(w * xs.x + xd.x, w * xs.y + xd.y,
                                 w * xs.z + xd.z, w * xs.w + xd.w);
        red_add_v4(&g_xv2[(size_t)sd.y * CC + part * 4], msg);
    }
}
// all 3 branches in one launch (blockIdx.y = branch)
__global__ void __launch_bounds__(256) edge_sage3() {
    const int by = blockIdx.y;
    const int n = g_ecnt[3 + by];
    const int2* list = g_elist[3 + by];
    float* sbuf = g_bs + (size_t)by * NC;
    int*   cnt  = g_bcnt + by * NNODE;
    const float4* H4 = (const float4*)(g_bh + (size_t)by * NC);
    const int part = threadIdx.x & 31;
    for (int i = blockIdx.x * 8 + (threadIdx.x >> 5); i < n; i += gridDim.x * 8) {
        int2 sd = list[i];
        float4 hs = __ldg(&H4[(size_t)sd.x * 32 + part]);
        red_add_v4(&sbuf[(size_t)sd.y * CC + part * 4], hs);
        if (part == 0) atomicAdd(&cnt[sd.y], 1);
    }
}

// a_res = a @ fc_W + fc_b
__global__ void ares_kernel(const float* __restrict__ fcW, const float* __restrict__ fcb) {
    int warp = (blockIdx.x * blockDim.x + threadIdx.x) >> 5;
    int lane = threadIdx.x & 31;
    if (warp >= NNODE) return;
    const float* ap = &g_a[(size_t)warp * CC];
    float acc = 0.f;
    #pragma unroll
    for (int k = 0; k < 4; k++) acc += ap[lane + 32*k] * fcW[lane + 32*k];
    #pragma unroll
    for (int o = 16; o > 0; o >>= 1) acc += __shfl_xor_sync(0xffffffffu, acc, o);
    if (lane == 0) g_ares[warp] = acc + fcb[0];
}

// ===== final SAGE GEMM, output rows only, 3 branches, mean folded, red.v2 -> d_out ===
__global__ void __launch_bounds__(256) gemm_sage3(
    const float* __restrict__ Wl, const float* __restrict__ bl,
    const float* __restrict__ Wr, float* __restrict__ dout, int node_stride)
{
    __shared__ float As[2][128][20];
    __shared__ float Bs[2][16][136];
    const int by = blockIdx.y;
    const float* A1 = g_bs + (size_t)by * NC;
    const float* A2 = g_bh + (size_t)by * NC;
    const int*  cnt = g_bcnt + by * NNODE;
    const int tid  = threadIdx.x;
    const int warp = tid >> 5, lane = tid & 31;
    const int wm = warp >> 1;
    const int wn = warp & 1;
    const int lq = lane >> 2, lr = lane & 3;
    const int node0 = blockIdx.x * node_stride;
    const int out0  = blockIdx.x * 128;

    float rinv[4];
    #pragma unroll
    for (int j = 0; j < 4; j++) {
        int c = cnt[node0 + wm * 32 + lq + j * 8];
        rinv[j] = 1.f / (float)(c > 1 ? c : 1);
    }

    float acc[2][8][4];
    #pragma unroll
    for (int mt = 0; mt < 2; mt++)
        #pragma unroll
        for (int nt = 0; nt < 8; nt++)
            #pragma unroll
            for (int i = 0; i < 4; i++) acc[mt][nt][i] = 0.f;

    const int nk = 16;     // concat K=256
    {
        #pragma unroll
        for (int l = 0; l < 2; l++) {
            int idx = tid * 2 + l;
            int r = idx >> 2, c4 = (idx & 3) * 4;
            cpasync16(&As[0][r][c4], &A1[(size_t)(node0 + r) * CC + c4]);
        }
        #pragma unroll
        for (int l = 0; l < 2; l++) {
            int idx = tid * 2 + l;
            int r = idx >> 5, c4 = (idx & 31) * 4;
            cpasync16(&Bs[0][r][c4], &Wl[(size_t)r * CC + c4]);
        }
        CP_COMMIT();
    }

    for (int kk = 0; kk < nk; kk++) {
        int st = kk & 1;
        if (kk + 1 < nk) {
            int ns = st ^ 1;
            int kn = kk + 1;
            const float* Asrc = (kn < 8) ? A1 : A2;
            const float* Wsrc = (kn < 8) ? Wl : Wr;
            int k0 = (kn & 7) * 16;
            #pragma unroll
            for (int l = 0; l < 2; l++) {
                int idx = tid * 2 + l;
                int r = idx >> 2, c4 = (idx & 3) * 4;
                cpasync16(&As[ns][r][c4], &Asrc[(size_t)(node0 + r) * CC + k0 + c4]);
            }
            #pragma unroll
            for (int l = 0; l < 2; l++) {
                int idx = tid * 2 + l;
                int r = idx >> 5, c4 = (idx & 31) * 4;
                cpasync16(&Bs[ns][r][c4], &Wsrc[(size_t)(k0 + r) * CC + c4]);
            }
            CP_COMMIT();
            CP_WAIT(1);
        } else {
            CP_WAIT(0);
        }
        __syncthreads();

        const bool isA1 = (kk < 8);
        #pragma unroll
        for (int kss = 0; kss < 2; kss++) {
            const int k0 = kss * 8;
            uint32_t af[2][4], bf[8][2];
            const int arow0 = wm * 32 + lq;
            #pragma unroll
            for (int mt = 0; mt < 2; mt++) {
                int r = arow0 + mt * 16;
                float s0 = isA1 ? rinv[mt*2    ] : 1.f;
                float s1 = isA1 ? rinv[mt*2 + 1] : 1.f;
                af[mt][0] = f2tf(As[st][r    ][k0 + lr    ] * s0);
                af[mt][1] = f2tf(As[st][r + 8][k0 + lr    ] * s1);
                af[mt][2] = f2tf(As[st][r    ][k0 + lr + 4] * s0);
                af[mt][3] = f2tf(As[st][r + 8][k0 + lr + 4] * s1);
            }
            #pragma unroll
            for (int nt = 0; nt < 8; nt++) {
                int col = wn * 64 + nt * 8 + lq;
                bf[nt][0] = f2tf(Bs[st][k0 + lr    ][col]);
                bf[nt][1] = f2tf(Bs[st][k0 + lr + 4][col]);
            }
            #pragma unroll
            for (int mt = 0; mt < 2; mt++)
                #pragma unroll
                for (int nt = 0; nt < 8; nt++)
                    mma_tf32(acc[mt][nt], af[mt], bf[nt]);
        }
        __syncthreads();
    }

    #pragma unroll
    for (int mt = 0; mt < 2; mt++) {
        #pragma unroll
        for (int half = 0; half < 2; half++) {
            int orow = out0 + wm * 32 + mt * 16 + lq + half * 8;
            #pragma unroll
            for (int nt = 0; nt < 8; nt++) {
                int col = wn * 64 + nt * 8 + lr * 2;
                float v0 = fmaxf(acc[mt][nt][half * 2 + 0] + bl[col    ], 0.f);
                float v1 = fmaxf(acc[mt][nt][half * 2 + 1] + bl[col + 1], 0.f);
                red_add_v2(&dout[(size_t)orow * CC + col], v0, v1);
            }
        }
    }
}

// ---------------- host orchestration ----------------
static inline void* symv(const void* s) {
    void* p = nullptr;
    cudaGetSymbolAddress(&p, (const void*)s);
    return p;
}

extern "C" void kernel_launch(void* const* d_in, const int* in_sizes, int n_in,
                              void* d_out, int out_size) {
    const float* x_visual = (const float*)d_in[0];
    const float* x_audio  = (const float*)d_in[1];
    const float* W011 = (const float*)d_in[2];  const float* b011 = (const float*)d_in[3];
    const float* W012 = (const float*)d_in[4];  const float* b012 = (const float*)d_in[5];
    const float* ecW1[4] = {(const float*)d_in[6],  (const float*)d_in[10],
                            (const float*)d_in[14], (const float*)d_in[18]};
    const float* ecb1[4] = {(const float*)d_in[7],  (const float*)d_in[11],
                            (const float*)d_in[15], (const float*)d_in[19]};
    const float* ecW2[4] = {(const float*)d_in[8],  (const float*)d_in[12],
                            (const float*)d_in[16], (const float*)d_in[20]};
    const float* ecb2[4] = {(const float*)d_in[9],  (const float*)d_in[13],
                            (const float*)d_in[17], (const float*)d_in[21]};
    const float* Wl  = (const float*)d_in[22];
    const float* bl  = (const float*)d_in[23];
    const float* Wr  = (const float*)d_in[24];
    const float* fcW = (const float*)d_in[25];
    const float* fcb = (const float*)d_in[26];
    const int*   eidx = (const int*)d_in[27];
    const int*   attr = (const int*)d_in[28];
    const int E = in_sizes[27] / 2;
    const int* srcp = eidx;
    const int* dstp = eidx + E;

    float* pxag = (float*)symv(g_xag);
    float* pP   = (float*)symv(g_P);    float* pQ   = (float*)symv(g_Q);
    float* pa   = (float*)symv(g_a);    float* pxv2 = (float*)symv(g_xv2);
    float* pwp  = (float*)symv(g_WP);
    int*   pecnt= (int*)symv(g_ecnt);
    int*   pbcnt= (int*)symv(g_bcnt);
    int2*  plist= (int2*)symv(g_elist);

    const int SCAT_GRID = 1184;

    cudaFuncSetAttribute(conv_tcA, cudaFuncAttributeMaxDynamicSharedMemorySize, SMEM_CONV_BYTES);
    cudaFuncSetAttribute(conv_tc3, cudaFuncAttributeMaxDynamicSharedMemorySize, SMEM_CONV_BYTES);

    // zeroing + small memsets
    cudaMemsetAsync(pecnt, 0, 6 * sizeof(int));
    cudaMemsetAsync(pbcnt, 0, 3 * NNODE * sizeof(int));
    cudaMemsetAsync(d_out, 0, (size_t)out_size * sizeof(float));
    zero_all<<<NC/4/256, 256>>>();

    compact_edges<<<(E + 255)/256, 256>>>(srcp, dstp, attr, E);
    prep_wp<<<(4*CC*CC + 255)/256, 256>>>(ecW1[0], ecW1[1], ecW1[2], ecW1[3]);

    // fused input projections -> g_x (plain store)
    gemm_proj<<<NNODE/64, 256>>>(x_visual, W011, b011, x_audio, W012, b012);

    // xa_g = relu(seg_max over vpa edges of x[dst]+x[src])
    edge_vpa2<<<SCAT_GRID, 256>>>();

    // convA: a = relu(EdgeConv(xa_g; attr==-2))
    gemm_dualA<<<NNODE/64, 256>>>(pxag, pwp, ecb1[0], ecW1[0]+CC*CC, pP, pQ);
    conv_tcA<<<296, 256, SMEM_CONV_BYTES>>>(plist + 1*EMAX, pecnt + 1,
                                            ecW2[0], ecb2[0], pP, pQ, pa);

    ares_kernel<<<NNODE/8, 256>>>(fcW, fcb);

    // xv2 raw sums (relu folded into gemm_dual3's A conversion)
    edge_acv2<<<SCAT_GRID, 256>>>();

    // 3 branches batched per stage
    Dual3Args da;
    Conv3Args ca;
    for (int b = 0; b < 3; b++) {
        da.W1[b] = pwp + (b + 1) * CC * CC;
        da.b1[b] = ecb1[b + 1];
        da.W2[b] = ecW1[b + 1] + CC * CC;
        ca.W2[b] = ecW2[b + 1];
        ca.b2[b] = ecb2[b + 1];
    }
    gemm_dual3<<<dim3(NNODE/64, 3), 256>>>(pxv2, da);
    conv_tc3<<<dim3(148, 3), 256, SMEM_CONV_BYTES>>>(ca);
    edge_sage3<<<dim3(592, 3), 256>>>();

    // final: dout[g*128+r] = sum_b relu(mean_b@Wl + bl + h_b@Wr) on output rows only
    int groups = out_size / (TT * CC);      // 64
    int step   = MV / groups;               // speakers*T = 384
    gemm_sage3<<<dim3(groups, 3), 256>>>(Wl, bl, Wr, (float*)d_out, step);
}